// round 1
// baseline (speedup 1.0000x reference)
#include <cuda_runtime.h>
#include <cuda_bf16.h>
#include <cstdint>

// Problem constants
#define D_MODEL 1024
#define N_HEADS 8
#define N_KV 2
#define HEAD_DIM 128
#define D_LAT 32
#define N_REP 4
#define BATCH 2
#define SEQ 2048
#define M_TOK (BATCH*SEQ)          // 4096 rows
#define KV_COLS (N_KV*HEAD_DIM)    // 256

// ---------------- scratch (static __device__, no allocations) ----------------
// layout: q[4096*1024] | k[4096*256] | v[4096*256] | y[4096*1024] | wke[1024*256] | wve[1024*256]
#define OFF_Q   0
#define OFF_K   (4096*1024)
#define OFF_V   (OFF_K + 4096*256)
#define OFF_Y   (OFF_V + 4096*256)
#define OFF_WKE (OFF_Y + 4096*1024)
#define OFF_WVE (OFF_WKE + 1024*256)
#define SCRATCH_FLOATS (OFF_WVE + 1024*256)
__device__ float g_scratch[SCRATCH_FLOATS];

// ---------------- effective up-projected weights ----------------
// wke[c][h*128+d] = sum_l wk_down[c*64 + h*32 + l] * wk_up[l*128 + d]
__global__ void eff_weights_kernel(const float* __restrict__ wkd,
                                   const float* __restrict__ wvd,
                                   const float* __restrict__ wku,
                                   const float* __restrict__ wvu,
                                   float* __restrict__ wke,
                                   float* __restrict__ wve) {
    int idx = blockIdx.x * blockDim.x + threadIdx.x;   // 0 .. 2*262144-1
    int which = idx >> 18;
    int e = idx & ((1 << 18) - 1);
    int c = e >> 8;
    int hd = e & 255;
    int h = hd >> 7;
    int d = hd & 127;
    const float* wd = which ? wvd : wkd;
    const float* wu = which ? wvu : wku;
    float s = 0.f;
#pragma unroll
    for (int l = 0; l < D_LAT; l++)
        s += wd[c * (N_KV * D_LAT) + h * D_LAT + l] * wu[l * HEAD_DIM + d];
    (which ? wve : wke)[e] = s;
}

// ---------------- generic 128x128x8 tiled SGEMM (row-major A[M,K], B[K,N]) ----------------
__global__ __launch_bounds__(256) void sgemm128(int M, int N, int K,
                                                const float* __restrict__ A,
                                                const float* __restrict__ B,
                                                float* __restrict__ C) {
    __shared__ float As[8 * 128];   // transposed: As[k][row]
    __shared__ float Bs[8 * 128];   // Bs[k][col]
    const int tid = threadIdx.x;
    const int tr = tid >> 4;        // 0..15
    const int tc = tid & 15;        // 0..15
    const int row0 = blockIdx.y * 128;
    const int col0 = blockIdx.x * 128;

    float acc[8][8];
#pragma unroll
    for (int i = 0; i < 8; i++)
#pragma unroll
        for (int j = 0; j < 8; j++) acc[i][j] = 0.f;

    const int arow = tid >> 1;            // 0..127
    const int acol = (tid & 1) << 2;      // 0 or 4
    const int brow = tid >> 5;            // 0..7
    const int bcol = (tid & 31) << 2;     // 0..124

    for (int k0 = 0; k0 < K; k0 += 8) {
        float4 av = *(const float4*)(A + (size_t)(row0 + arow) * K + k0 + acol);
        As[(acol + 0) * 128 + arow] = av.x;
        As[(acol + 1) * 128 + arow] = av.y;
        As[(acol + 2) * 128 + arow] = av.z;
        As[(acol + 3) * 128 + arow] = av.w;
        float4 bv = *(const float4*)(B + (size_t)(k0 + brow) * N + col0 + bcol);
        *(float4*)(&Bs[brow * 128 + bcol]) = bv;
        __syncthreads();
#pragma unroll
        for (int kk = 0; kk < 8; kk++) {
            float a[8], b[8];
#pragma unroll
            for (int i = 0; i < 8; i++) a[i] = As[kk * 128 + tr + (i << 4)];
#pragma unroll
            for (int j = 0; j < 8; j++) b[j] = Bs[kk * 128 + tc + (j << 4)];
#pragma unroll
            for (int i = 0; i < 8; i++)
#pragma unroll
                for (int j = 0; j < 8; j++) acc[i][j] += a[i] * b[j];
        }
        __syncthreads();
    }
#pragma unroll
    for (int i = 0; i < 8; i++) {
        int r = row0 + tr + (i << 4);
#pragma unroll
        for (int j = 0; j < 8; j++)
            C[(size_t)r * N + col0 + tc + (j << 4)] = acc[i][j];
    }
}

// ---------------- causal GQA flash attention (fp32) ----------------
// Q tile 64 rows of one q-head, loop K/V tiles of 64 with online softmax.
// Thread layout: ty=tid>>4 (16), tx=tid&15 (16).
//   S micro: rows 4ty+i (i<4), cols tx+16j (j<4)
//   O micro: rows 4ty+i (i<4), cols tx+16j (j<8)
#define FA_QS 129          // padded row stride for Q/K/V tiles
#define FA_SS 65           // padded row stride for P tile
#define FA_SMEM ((3*64*FA_QS + 64*FA_SS)*4)

__global__ __launch_bounds__(256) void flash_attn_kernel(const float* __restrict__ qg,
                                                         const float* __restrict__ kg,
                                                         const float* __restrict__ vg,
                                                         float* __restrict__ yg) {
    extern __shared__ float sm[];
    float* Qs = sm;                    // 64 x FA_QS
    float* Ks = Qs + 64 * FA_QS;
    float* Vs = Ks + 64 * FA_QS;
    float* Ss = Vs + 64 * FA_QS;       // 64 x FA_SS

    const int qi = blockIdx.x;         // q tile index (0..31)
    const int hq = blockIdx.y;         // q head (0..7)
    const int b  = blockIdx.z;
    const int kv = hq >> 2;            // GQA group
    const int tid = threadIdx.x;
    const int ty = tid >> 4;
    const int tx = tid & 15;
    const int q0 = qi * 64;
    const float scale = 0.08838834764831845f;   // 1/sqrt(128)

    const float* qbase = qg + ((size_t)b * SEQ + q0) * (N_HEADS * HEAD_DIM) + hq * HEAD_DIM;
    const float* kbase = kg + ((size_t)b * SEQ) * KV_COLS + kv * HEAD_DIM;
    const float* vbase = vg + ((size_t)b * SEQ) * KV_COLS + kv * HEAD_DIM;

    // load Q tile (scale folded in)
    for (int idx = tid; idx < 64 * 128; idx += 256) {
        int r = idx >> 7, c = idx & 127;
        Qs[r * FA_QS + c] = qbase[(size_t)r * (N_HEADS * HEAD_DIM) + c] * scale;
    }

    float m_i[4], l_i[4], o[4][8];
#pragma unroll
    for (int i = 0; i < 4; i++) {
        m_i[i] = -1e30f; l_i[i] = 0.f;
#pragma unroll
        for (int j = 0; j < 8; j++) o[i][j] = 0.f;
    }

    for (int kc = 0; kc <= qi; kc++) {
        __syncthreads();
        for (int idx = tid; idx < 64 * 128; idx += 256) {
            int r = idx >> 7, c = idx & 127;
            Ks[r * FA_QS + c] = kbase[(size_t)(kc * 64 + r) * KV_COLS + c];
            Vs[r * FA_QS + c] = vbase[(size_t)(kc * 64 + r) * KV_COLS + c];
        }
        __syncthreads();

        // S = Q @ K^T
        float s[4][4];
#pragma unroll
        for (int i = 0; i < 4; i++)
#pragma unroll
            for (int j = 0; j < 4; j++) s[i][j] = 0.f;
#pragma unroll 4
        for (int d = 0; d < 128; d++) {
            float qv[4], kvv[4];
#pragma unroll
            for (int i = 0; i < 4; i++) qv[i] = Qs[(4 * ty + i) * FA_QS + d];
#pragma unroll
            for (int j = 0; j < 4; j++) kvv[j] = Ks[(tx + 16 * j) * FA_QS + d];
#pragma unroll
            for (int i = 0; i < 4; i++)
#pragma unroll
                for (int j = 0; j < 4; j++) s[i][j] += qv[i] * kvv[j];
        }

        // causal mask on the diagonal tile
        if (kc == qi) {
#pragma unroll
            for (int i = 0; i < 4; i++) {
                int r = q0 + 4 * ty + i;
#pragma unroll
                for (int j = 0; j < 4; j++) {
                    int c = kc * 64 + tx + 16 * j;
                    if (c > r) s[i][j] = -1e30f;
                }
            }
        }

        // online softmax update (row stats reduced over the 16 tx lanes)
#pragma unroll
        for (int i = 0; i < 4; i++) {
            float mx = fmaxf(fmaxf(s[i][0], s[i][1]), fmaxf(s[i][2], s[i][3]));
#pragma unroll
            for (int off = 8; off >= 1; off >>= 1)
                mx = fmaxf(mx, __shfl_xor_sync(0xffffffffu, mx, off, 16));
            float m_new = fmaxf(m_i[i], mx);
            float alpha = __expf(m_i[i] - m_new);
            float rs = 0.f;
#pragma unroll
            for (int j = 0; j < 4; j++) {
                float p = __expf(s[i][j] - m_new);
                s[i][j] = p;
                rs += p;
            }
#pragma unroll
            for (int off = 8; off >= 1; off >>= 1)
                rs += __shfl_xor_sync(0xffffffffu, rs, off, 16);
            l_i[i] = l_i[i] * alpha + rs;
            m_i[i] = m_new;
#pragma unroll
            for (int j = 0; j < 8; j++) o[i][j] *= alpha;
#pragma unroll
            for (int j = 0; j < 4; j++)
                Ss[(4 * ty + i) * FA_SS + tx + 16 * j] = s[i][j];
        }
        __syncthreads();

        // O += P @ V
#pragma unroll 2
        for (int k = 0; k < 64; k++) {
            float vv[8];
#pragma unroll
            for (int j = 0; j < 8; j++) vv[j] = Vs[k * FA_QS + tx + 16 * j];
#pragma unroll
            for (int i = 0; i < 4; i++) {
                float p = Ss[(4 * ty + i) * FA_SS + k];
#pragma unroll
                for (int j = 0; j < 8; j++) o[i][j] += p * vv[j];
            }
        }
    }

    // epilogue: normalize and store
    float* ybase = yg + ((size_t)b * SEQ + q0) * (N_HEADS * HEAD_DIM) + hq * HEAD_DIM;
#pragma unroll
    for (int i = 0; i < 4; i++) {
        float inv = 1.f / l_i[i];
#pragma unroll
        for (int j = 0; j < 8; j++)
            ybase[(size_t)(4 * ty + i) * (N_HEADS * HEAD_DIM) + tx + 16 * j] = o[i][j] * inv;
    }
}

// ---------------- launch ----------------
extern "C" void kernel_launch(void* const* d_in, const int* in_sizes, int n_in,
                              void* d_out, int out_size) {
    const float* x   = (const float*)d_in[0];
    const float* wq  = (const float*)d_in[1];
    const float* wkd = (const float*)d_in[2];
    const float* wvd = (const float*)d_in[3];
    const float* wku = (const float*)d_in[4];
    const float* wvu = (const float*)d_in[5];
    const float* wo  = (const float*)d_in[6];
    float* out = (float*)d_out;

    float* scratch = nullptr;
    cudaGetSymbolAddress((void**)&scratch, g_scratch);
    float* qb  = scratch + OFF_Q;
    float* kb  = scratch + OFF_K;
    float* vb  = scratch + OFF_V;
    float* yb  = scratch + OFF_Y;
    float* wke = scratch + OFF_WKE;
    float* wve = scratch + OFF_WVE;

    // 1. fold latent up-projection into the down weights
    eff_weights_kernel<<<2048, 256>>>(wkd, wvd, wku, wvu, wke, wve);

    // 2. projections
    sgemm128<<<dim3(N_HEADS * HEAD_DIM / 128, M_TOK / 128), 256>>>(M_TOK, N_HEADS * HEAD_DIM, D_MODEL, x, wq, qb);
    sgemm128<<<dim3(KV_COLS / 128, M_TOK / 128), 256>>>(M_TOK, KV_COLS, D_MODEL, x, wke, kb);
    sgemm128<<<dim3(KV_COLS / 128, M_TOK / 128), 256>>>(M_TOK, KV_COLS, D_MODEL, x, wve, vb);

    // 3. causal GQA flash attention
    cudaFuncSetAttribute(flash_attn_kernel, cudaFuncAttributeMaxDynamicSharedMemorySize, FA_SMEM);
    flash_attn_kernel<<<dim3(SEQ / 64, N_HEADS, BATCH), 256, FA_SMEM>>>(qb, kb, vb, yb);

    // 4. output projection
    sgemm128<<<dim3(D_MODEL / 128, M_TOK / 128), 256>>>(M_TOK, D_MODEL, N_HEADS * HEAD_DIM, yb, wo, out);
}

// round 2
// speedup vs baseline: 1.7321x; 1.7321x over previous
#include <cuda_runtime.h>
#include <cuda_bf16.h>
#include <cstdint>

// Problem constants
#define D_MODEL 1024
#define N_HEADS 8
#define N_KV 2
#define HEAD_DIM 128
#define D_LAT 32
#define N_REP 4
#define BATCH 2
#define SEQ 2048
#define M_TOK (BATCH*SEQ)          // 4096 rows
#define KV_COLS (N_KV*HEAD_DIM)    // 256
#define KV_N 512                   // fused K|V width

// ---------------- scratch ----------------
// q[4096*1024] | kv[4096*512] | y[4096*1024] | wkve[1024*512]
#define OFF_Q   0
#define OFF_KV  (4096*1024)
#define OFF_Y   (OFF_KV + 4096*512)
#define OFF_WKVE (OFF_Y + 4096*1024)
#define SCRATCH_FLOATS (OFF_WKVE + 1024*512)
__device__ float g_scratch[SCRATCH_FLOATS];

// ---------------- effective fused up-projected weights ----------------
// wkve[c][n]: n<256 -> K eff, n>=256 -> V eff
__global__ void eff_weights_kernel(const float* __restrict__ wkd,
                                   const float* __restrict__ wvd,
                                   const float* __restrict__ wku,
                                   const float* __restrict__ wvu,
                                   float* __restrict__ wkve) {
    int idx = blockIdx.x * blockDim.x + threadIdx.x;   // 0 .. 1024*512-1
    int c = idx >> 9;
    int n = idx & 511;
    int which = n >> 8;          // 0 = K, 1 = V
    int hd = n & 255;
    int h = hd >> 7;
    int d = hd & 127;
    const float* wd = which ? wvd : wkd;
    const float* wu = which ? wvu : wku;
    float s = 0.f;
#pragma unroll
    for (int l = 0; l < D_LAT; l++)
        s += wd[c * (N_KV * D_LAT) + h * D_LAT + l] * wu[l * HEAD_DIM + d];
    wkve[idx] = s;
}

// ---------------- tf32 mma.sync GEMM: C[M,N] = A[M,K] @ B[K,N], row-major ----------------
// Tile 128x128, BK=32. 256 threads = 8 warps (2 x 4). Warp tile 64x32 = 4x4 m16n8k8.
#define MMA_AS 36        // padded A smem row stride (floats)
#define MMA_BS 136       // padded B smem row stride (floats)
#define A_TILE (128*MMA_AS)
#define B_TILE (32*MMA_BS)
#define MM_SMEM ((2*A_TILE + 2*B_TILE)*4)

__device__ __forceinline__ uint32_t f2tf(float x) {
    uint32_t u;
    asm("cvt.rna.tf32.f32 %0, %1;" : "=r"(u) : "f"(x));
    return u;
}

__global__ __launch_bounds__(256, 1) void mm_tf32(int M, int N, int K,
                                                  const float* __restrict__ A,
                                                  const float* __restrict__ B,
                                                  float* __restrict__ C) {
    extern __shared__ uint32_t smu[];
    uint32_t* As = smu;                 // [2][A_TILE]
    uint32_t* Bs = smu + 2 * A_TILE;    // [2][B_TILE]

    const int tid = threadIdx.x;
    const int w = tid >> 5;
    const int wm = w & 1;               // 0..1  -> 64 rows
    const int wn = w >> 1;              // 0..3  -> 32 cols
    const int lane = tid & 31;
    const int group = lane >> 2;        // 0..7
    const int tig = lane & 3;           // 0..3

    const int row0 = blockIdx.y * 128;
    const int col0 = blockIdx.x * 128;

    // global load coordinates (register-staged, 4 float4 per tile per operand)
    const int ar = tid >> 3;            // 0..31  (rows ar, ar+32, ar+64, ar+96)
    const int ac = (tid & 7) << 2;      // 0..28
    const int br = tid >> 5;            // 0..7   (rows br, br+8, br+16, br+24)
    const int bc = (tid & 31) << 2;     // 0..124

    float4 la[4], lb[4];

    auto gload = [&](int kt) {
#pragma unroll
        for (int i = 0; i < 4; i++)
            la[i] = *(const float4*)(A + (size_t)(row0 + ar + 32 * i) * K + kt + ac);
#pragma unroll
        for (int i = 0; i < 4; i++)
            lb[i] = *(const float4*)(B + (size_t)(kt + br + 8 * i) * N + col0 + bc);
    };
    auto sstore = [&](int p) {
        uint32_t* Ap = As + p * A_TILE;
        uint32_t* Bp = Bs + p * B_TILE;
#pragma unroll
        for (int i = 0; i < 4; i++) {
            uint4 u = make_uint4(f2tf(la[i].x), f2tf(la[i].y), f2tf(la[i].z), f2tf(la[i].w));
            *(uint4*)(Ap + (ar + 32 * i) * MMA_AS + ac) = u;
        }
#pragma unroll
        for (int i = 0; i < 4; i++) {
            uint4 u = make_uint4(f2tf(lb[i].x), f2tf(lb[i].y), f2tf(lb[i].z), f2tf(lb[i].w));
            *(uint4*)(Bp + (br + 8 * i) * MMA_BS + bc) = u;
        }
    };

    float c[4][4][4];
#pragma unroll
    for (int i = 0; i < 4; i++)
#pragma unroll
        for (int j = 0; j < 4; j++)
#pragma unroll
            for (int r = 0; r < 4; r++) c[i][j][r] = 0.f;

    const int nt = K >> 5;
    gload(0);
    sstore(0);
    __syncthreads();

    for (int t = 0; t < nt; t++) {
        if (t + 1 < nt) gload((t + 1) << 5);
        const uint32_t* Ap = As + (t & 1) * A_TILE;
        const uint32_t* Bp = Bs + (t & 1) * B_TILE;
#pragma unroll
        for (int kk = 0; kk < 4; kk++) {
            const int k8 = kk << 3;
            uint32_t a[4][4], b[4][2];
#pragma unroll
            for (int i = 0; i < 4; i++) {
                int rb = wm * 64 + i * 16 + group;
                a[i][0] = Ap[rb * MMA_AS + k8 + tig];
                a[i][1] = Ap[(rb + 8) * MMA_AS + k8 + tig];
                a[i][2] = Ap[rb * MMA_AS + k8 + tig + 4];
                a[i][3] = Ap[(rb + 8) * MMA_AS + k8 + tig + 4];
            }
#pragma unroll
            for (int j = 0; j < 4; j++) {
                int cb = wn * 32 + j * 8 + group;
                b[j][0] = Bp[(k8 + tig) * MMA_BS + cb];
                b[j][1] = Bp[(k8 + tig + 4) * MMA_BS + cb];
            }
#pragma unroll
            for (int i = 0; i < 4; i++)
#pragma unroll
                for (int j = 0; j < 4; j++)
                    asm volatile(
                        "mma.sync.aligned.m16n8k8.row.col.f32.tf32.tf32.f32 "
                        "{%0,%1,%2,%3},{%4,%5,%6,%7},{%8,%9},{%0,%1,%2,%3};"
                        : "+f"(c[i][j][0]), "+f"(c[i][j][1]), "+f"(c[i][j][2]), "+f"(c[i][j][3])
                        : "r"(a[i][0]), "r"(a[i][1]), "r"(a[i][2]), "r"(a[i][3]),
                          "r"(b[j][0]), "r"(b[j][1]));
        }
        if (t + 1 < nt) sstore((t + 1) & 1);
        __syncthreads();
    }

    // epilogue
#pragma unroll
    for (int i = 0; i < 4; i++) {
        int r = row0 + wm * 64 + i * 16 + group;
#pragma unroll
        for (int j = 0; j < 4; j++) {
            int cc = col0 + wn * 32 + j * 8 + tig * 2;
            *(float2*)(C + (size_t)r * N + cc) = make_float2(c[i][j][0], c[i][j][1]);
            *(float2*)(C + (size_t)(r + 8) * N + cc) = make_float2(c[i][j][2], c[i][j][3]);
        }
    }
}

// ---------------- causal GQA flash attention (fp32) ----------------
#define FA_QS 129          // padded row stride for Q/K/V tiles
#define FA_SS 65           // padded row stride for P tile
#define FA_SMEM ((3*64*FA_QS + 64*FA_SS)*4)

__global__ __launch_bounds__(256) void flash_attn_kernel(const float* __restrict__ qg,
                                                         const float* __restrict__ kvg,
                                                         float* __restrict__ yg) {
    extern __shared__ float sm[];
    float* Qs = sm;                    // 64 x FA_QS
    float* Ks = Qs + 64 * FA_QS;
    float* Vs = Ks + 64 * FA_QS;
    float* Ss = Vs + 64 * FA_QS;       // 64 x FA_SS

    const int qi = blockIdx.x;         // q tile index (0..31)
    const int hq = blockIdx.y;         // q head (0..7)
    const int b  = blockIdx.z;
    const int kv = hq >> 2;            // GQA group
    const int tid = threadIdx.x;
    const int ty = tid >> 4;
    const int tx = tid & 15;
    const int q0 = qi * 64;
    const float scale = 0.08838834764831845f;   // 1/sqrt(128)

    const float* qbase = qg + ((size_t)b * SEQ + q0) * (N_HEADS * HEAD_DIM) + hq * HEAD_DIM;
    const float* kbase = kvg + ((size_t)b * SEQ) * KV_N + kv * HEAD_DIM;
    const float* vbase = kbase + KV_COLS;

    for (int idx = tid; idx < 64 * 128; idx += 256) {
        int r = idx >> 7, c = idx & 127;
        Qs[r * FA_QS + c] = qbase[(size_t)r * (N_HEADS * HEAD_DIM) + c] * scale;
    }

    float m_i[4], l_i[4], o[4][8];
#pragma unroll
    for (int i = 0; i < 4; i++) {
        m_i[i] = -1e30f; l_i[i] = 0.f;
#pragma unroll
        for (int j = 0; j < 8; j++) o[i][j] = 0.f;
    }

    for (int kc = 0; kc <= qi; kc++) {
        __syncthreads();
        for (int idx = tid; idx < 64 * 128; idx += 256) {
            int r = idx >> 7, c = idx & 127;
            Ks[r * FA_QS + c] = kbase[(size_t)(kc * 64 + r) * KV_N + c];
            Vs[r * FA_QS + c] = vbase[(size_t)(kc * 64 + r) * KV_N + c];
        }
        __syncthreads();

        float s[4][4];
#pragma unroll
        for (int i = 0; i < 4; i++)
#pragma unroll
            for (int j = 0; j < 4; j++) s[i][j] = 0.f;
#pragma unroll 4
        for (int d = 0; d < 128; d++) {
            float qv[4], kvv[4];
#pragma unroll
            for (int i = 0; i < 4; i++) qv[i] = Qs[(4 * ty + i) * FA_QS + d];
#pragma unroll
            for (int j = 0; j < 4; j++) kvv[j] = Ks[(tx + 16 * j) * FA_QS + d];
#pragma unroll
            for (int i = 0; i < 4; i++)
#pragma unroll
                for (int j = 0; j < 4; j++) s[i][j] += qv[i] * kvv[j];
        }

        if (kc == qi) {
#pragma unroll
            for (int i = 0; i < 4; i++) {
                int r = q0 + 4 * ty + i;
#pragma unroll
                for (int j = 0; j < 4; j++) {
                    int cidx = kc * 64 + tx + 16 * j;
                    if (cidx > r) s[i][j] = -1e30f;
                }
            }
        }

#pragma unroll
        for (int i = 0; i < 4; i++) {
            float mx = fmaxf(fmaxf(s[i][0], s[i][1]), fmaxf(s[i][2], s[i][3]));
#pragma unroll
            for (int off = 8; off >= 1; off >>= 1)
                mx = fmaxf(mx, __shfl_xor_sync(0xffffffffu, mx, off, 16));
            float m_new = fmaxf(m_i[i], mx);
            float alpha = __expf(m_i[i] - m_new);
            float rs = 0.f;
#pragma unroll
            for (int j = 0; j < 4; j++) {
                float p = __expf(s[i][j] - m_new);
                s[i][j] = p;
                rs += p;
            }
#pragma unroll
            for (int off = 8; off >= 1; off >>= 1)
                rs += __shfl_xor_sync(0xffffffffu, rs, off, 16);
            l_i[i] = l_i[i] * alpha + rs;
            m_i[i] = m_new;
#pragma unroll
            for (int j = 0; j < 8; j++) o[i][j] *= alpha;
#pragma unroll
            for (int j = 0; j < 4; j++)
                Ss[(4 * ty + i) * FA_SS + tx + 16 * j] = s[i][j];
        }
        __syncthreads();

#pragma unroll 2
        for (int k = 0; k < 64; k++) {
            float vv[8];
#pragma unroll
            for (int j = 0; j < 8; j++) vv[j] = Vs[k * FA_QS + tx + 16 * j];
#pragma unroll
            for (int i = 0; i < 4; i++) {
                float p = Ss[(4 * ty + i) * FA_SS + k];
#pragma unroll
                for (int j = 0; j < 8; j++) o[i][j] += p * vv[j];
            }
        }
    }

    float* ybase = yg + ((size_t)b * SEQ + q0) * (N_HEADS * HEAD_DIM) + hq * HEAD_DIM;
#pragma unroll
    for (int i = 0; i < 4; i++) {
        float inv = 1.f / l_i[i];
#pragma unroll
        for (int j = 0; j < 8; j++)
            ybase[(size_t)(4 * ty + i) * (N_HEADS * HEAD_DIM) + tx + 16 * j] = o[i][j] * inv;
    }
}

// ---------------- launch ----------------
extern "C" void kernel_launch(void* const* d_in, const int* in_sizes, int n_in,
                              void* d_out, int out_size) {
    const float* x   = (const float*)d_in[0];
    const float* wq  = (const float*)d_in[1];
    const float* wkd = (const float*)d_in[2];
    const float* wvd = (const float*)d_in[3];
    const float* wku = (const float*)d_in[4];
    const float* wvu = (const float*)d_in[5];
    const float* wo  = (const float*)d_in[6];
    float* out = (float*)d_out;

    float* scratch = nullptr;
    cudaGetSymbolAddress((void**)&scratch, g_scratch);
    float* qb   = scratch + OFF_Q;
    float* kvb  = scratch + OFF_KV;
    float* yb   = scratch + OFF_Y;
    float* wkve = scratch + OFF_WKVE;

    // 1. fold latent up-projection into fused K|V effective weights
    eff_weights_kernel<<<2048, 256>>>(wkd, wvd, wku, wvu, wkve);

    // 2. projections (tf32 tensor cores)
    cudaFuncSetAttribute(mm_tf32, cudaFuncAttributeMaxDynamicSharedMemorySize, MM_SMEM);
    mm_tf32<<<dim3(1024 / 128, M_TOK / 128), 256, MM_SMEM>>>(M_TOK, 1024, D_MODEL, x, wq, qb);
    mm_tf32<<<dim3(KV_N / 128, M_TOK / 128), 256, MM_SMEM>>>(M_TOK, KV_N, D_MODEL, x, wkve, kvb);

    // 3. causal GQA flash attention
    cudaFuncSetAttribute(flash_attn_kernel, cudaFuncAttributeMaxDynamicSharedMemorySize, FA_SMEM);
    flash_attn_kernel<<<dim3(SEQ / 64, N_HEADS, BATCH), 256, FA_SMEM>>>(qb, kvb, yb);

    // 4. output projection
    mm_tf32<<<dim3(1024 / 128, M_TOK / 128), 256, MM_SMEM>>>(M_TOK, 1024, 1024, yb, wo, out);
}

// round 3
// speedup vs baseline: 2.6160x; 1.5103x over previous
#include <cuda_runtime.h>
#include <cuda_bf16.h>
#include <cstdint>

// Problem constants
#define D_MODEL 1024
#define N_HEADS 8
#define N_KV 2
#define HEAD_DIM 128
#define D_LAT 32
#define BATCH 2
#define SEQ 2048
#define M_TOK (BATCH*SEQ)          // 4096
#define KV_N 512                   // fused K|V width

// ---------------- scratch ----------------
#define OFF_Q   0
#define OFF_KV  (4096*1024)
#define OFF_Y   (OFF_KV + 4096*512)
#define OFF_WKVE (OFF_Y + 4096*1024)
#define SCRATCH_FLOATS (OFF_WKVE + 1024*512)
__device__ float g_scratch[SCRATCH_FLOATS];

// ---------------- split-bf16 helpers ----------------
// pack fp32 x as two bf16: uint = (lo16 << 16) | hi16, x ~= hi + lo
__device__ __forceinline__ uint32_t pk(float x) {
    __nv_bfloat16 h = __float2bfloat16(x);
    float hf = __bfloat162float(h);
    __nv_bfloat16 l = __float2bfloat16(x - hf);
    return ((uint32_t)__bfloat16_as_ushort(l) << 16) | (uint32_t)__bfloat16_as_ushort(h);
}
#define HIP(u0,u1) __byte_perm((u0),(u1),0x5410)
#define LOP(u0,u1) __byte_perm((u0),(u1),0x7632)

__device__ __forceinline__ void mma16(float* c, uint32_t a0, uint32_t a1, uint32_t a2, uint32_t a3,
                                      uint32_t b0, uint32_t b1) {
    asm volatile(
        "mma.sync.aligned.m16n8k16.row.col.f32.bf16.bf16.f32 "
        "{%0,%1,%2,%3},{%4,%5,%6,%7},{%8,%9},{%0,%1,%2,%3};"
        : "+f"(c[0]), "+f"(c[1]), "+f"(c[2]), "+f"(c[3])
        : "r"(a0), "r"(a1), "r"(a2), "r"(a3), "r"(b0), "r"(b1));
}

// ---------------- effective fused up-projected weights ----------------
__global__ void eff_weights_kernel(const float* __restrict__ wkd,
                                   const float* __restrict__ wvd,
                                   const float* __restrict__ wku,
                                   const float* __restrict__ wvu,
                                   float* __restrict__ wkve) {
    int idx = blockIdx.x * blockDim.x + threadIdx.x;   // 1024*512
    int c = idx >> 9;
    int n = idx & 511;
    int which = n >> 8;
    int hd = n & 255;
    int h = hd >> 7;
    int d = hd & 127;
    const float* wd = which ? wvd : wkd;
    const float* wu = which ? wvu : wku;
    float s = 0.f;
#pragma unroll
    for (int l = 0; l < D_LAT; l++)
        s += wd[c * (N_KV * D_LAT) + h * D_LAT + l] * wu[l * HEAD_DIM + d];
    wkve[idx] = s;
}

// ---------------- split-bf16 GEMM: C[M,N] = A[M,K] @ B[K,N] ----------------
// 128x128 tile, BK=32, 8 warps (2x4), warp tile 64x32.
#define MM_AS 40
#define MM_BS 140
#define MM_AT (128*MM_AS)
#define MM_BT (32*MM_BS)
#define MM_SMEM ((2*MM_AT + 2*MM_BT)*4)

__global__ __launch_bounds__(256) void mm_bf16x2(int M, int N, int K,
                                                 const float* __restrict__ A,
                                                 const float* __restrict__ B,
                                                 float* __restrict__ C) {
    extern __shared__ uint32_t smu[];
    uint32_t* As = smu;
    uint32_t* Bs = smu + 2 * MM_AT;

    const int tid = threadIdx.x;
    const int w = tid >> 5;
    const int wm = w & 1;
    const int wn = w >> 1;
    const int lane = tid & 31;
    const int g = lane >> 2;
    const int t = lane & 3;
    const int row0 = blockIdx.y * 128;
    const int col0 = blockIdx.x * 128;

    const int ar = tid >> 3;
    const int ac = (tid & 7) << 2;
    const int br = tid >> 5;
    const int bc = (tid & 31) << 2;

    float4 la[4], lb[4];
    auto gload = [&](int kt) {
#pragma unroll
        for (int i = 0; i < 4; i++)
            la[i] = *(const float4*)(A + (size_t)(row0 + ar + 32 * i) * K + kt + ac);
#pragma unroll
        for (int i = 0; i < 4; i++)
            lb[i] = *(const float4*)(B + (size_t)(kt + br + 8 * i) * N + col0 + bc);
    };
    auto sstore = [&](int p) {
        uint32_t* Ap = As + p * MM_AT;
        uint32_t* Bp = Bs + p * MM_BT;
#pragma unroll
        for (int i = 0; i < 4; i++) {
            uint4 u = make_uint4(pk(la[i].x), pk(la[i].y), pk(la[i].z), pk(la[i].w));
            *(uint4*)(Ap + (ar + 32 * i) * MM_AS + ac) = u;
        }
#pragma unroll
        for (int i = 0; i < 4; i++) {
            uint4 u = make_uint4(pk(lb[i].x), pk(lb[i].y), pk(lb[i].z), pk(lb[i].w));
            *(uint4*)(Bp + (br + 8 * i) * MM_BS + bc) = u;
        }
    };

    float c[4][4][4];
#pragma unroll
    for (int i = 0; i < 4; i++)
#pragma unroll
        for (int j = 0; j < 4; j++)
#pragma unroll
            for (int r = 0; r < 4; r++) c[i][j][r] = 0.f;

    const int nt = K >> 5;
    gload(0);
    sstore(0);
    __syncthreads();

    for (int tt = 0; tt < nt; tt++) {
        if (tt + 1 < nt) gload((tt + 1) << 5);
        const uint32_t* Ap = As + (tt & 1) * MM_AT;
        const uint32_t* Bp = Bs + (tt & 1) * MM_BT;
#pragma unroll
        for (int kk = 0; kk < 2; kk++) {
            const int k16 = kk << 4;
            uint32_t ahi[4][4], alo[4][4], bhi[4][2], blo[4][2];
#pragma unroll
            for (int i = 0; i < 4; i++) {
                int rb = wm * 64 + i * 16 + g;
                uint2 u0 = *(const uint2*)(Ap + rb * MM_AS + k16 + 2 * t);
                uint2 u1 = *(const uint2*)(Ap + (rb + 8) * MM_AS + k16 + 2 * t);
                uint2 u2 = *(const uint2*)(Ap + rb * MM_AS + k16 + 8 + 2 * t);
                uint2 u3 = *(const uint2*)(Ap + (rb + 8) * MM_AS + k16 + 8 + 2 * t);
                ahi[i][0] = HIP(u0.x, u0.y); alo[i][0] = LOP(u0.x, u0.y);
                ahi[i][1] = HIP(u1.x, u1.y); alo[i][1] = LOP(u1.x, u1.y);
                ahi[i][2] = HIP(u2.x, u2.y); alo[i][2] = LOP(u2.x, u2.y);
                ahi[i][3] = HIP(u3.x, u3.y); alo[i][3] = LOP(u3.x, u3.y);
            }
#pragma unroll
            for (int j = 0; j < 4; j++) {
                int cb = wn * 32 + j * 8 + g;
                uint32_t u0 = Bp[(k16 + 2 * t) * MM_BS + cb];
                uint32_t u1 = Bp[(k16 + 2 * t + 1) * MM_BS + cb];
                uint32_t u2 = Bp[(k16 + 2 * t + 8) * MM_BS + cb];
                uint32_t u3 = Bp[(k16 + 2 * t + 9) * MM_BS + cb];
                bhi[j][0] = HIP(u0, u1); blo[j][0] = LOP(u0, u1);
                bhi[j][1] = HIP(u2, u3); blo[j][1] = LOP(u2, u3);
            }
#pragma unroll
            for (int i = 0; i < 4; i++)
#pragma unroll
                for (int j = 0; j < 4; j++) {
                    mma16(c[i][j], ahi[i][0], ahi[i][1], ahi[i][2], ahi[i][3], bhi[j][0], bhi[j][1]);
                    mma16(c[i][j], ahi[i][0], ahi[i][1], ahi[i][2], ahi[i][3], blo[j][0], blo[j][1]);
                    mma16(c[i][j], alo[i][0], alo[i][1], alo[i][2], alo[i][3], bhi[j][0], bhi[j][1]);
                }
        }
        if (tt + 1 < nt) sstore((tt + 1) & 1);
        __syncthreads();
    }

#pragma unroll
    for (int i = 0; i < 4; i++) {
        int r = row0 + wm * 64 + i * 16 + g;
#pragma unroll
        for (int j = 0; j < 4; j++) {
            int cc = col0 + wn * 32 + j * 8 + t * 2;
            *(float2*)(C + (size_t)r * N + cc) = make_float2(c[i][j][0], c[i][j][1]);
            *(float2*)(C + (size_t)(r + 8) * N + cc) = make_float2(c[i][j][2], c[i][j][3]);
        }
    }
}

// ---------------- split-bf16 MMA flash attention ----------------
// BR=BC=64, 8 warps 2(row)x4(col). Warp S tile 32x16, warp O tile 32x32.
#define AT_QS 136
#define AT_VS 140
#define AT_PS 72
#define AT_NQ (64*AT_QS)
#define AT_NK (64*AT_QS)
#define AT_NV (64*AT_VS)
#define AT_NP (64*AT_PS)
#define AT_SMEM ((AT_NQ + AT_NK + AT_NV + AT_NP)*4 + 4*64*4*2)

__global__ __launch_bounds__(256) void flash_mma_kernel(const float* __restrict__ qg,
                                                        const float* __restrict__ kvg,
                                                        float* __restrict__ yg) {
    extern __shared__ uint32_t smu[];
    uint32_t* Qs = smu;
    uint32_t* Ks = Qs + AT_NQ;
    uint32_t* Vs = Ks + AT_NK;
    uint32_t* Ps = Vs + AT_NV;
    float* smax = (float*)(Ps + AT_NP);    // [4][64]
    float* ssum = smax + 4 * 64;           // [4][64]

    const int qi = (SEQ / 64 - 1) - blockIdx.x;   // heavy tiles first
    const int hq = blockIdx.y;
    const int b  = blockIdx.z;
    const int kvh = hq >> 2;
    const int tid = threadIdx.x;
    const int w = tid >> 5;
    const int wm = w & 1;                 // row half
    const int wn = w >> 1;                // col quarter
    const int lane = tid & 31;
    const int g = lane >> 2;
    const int t = lane & 3;
    const int q0 = qi * 64;
    const float scale = 0.08838834764831845f;

    const float* qbase = qg + ((size_t)b * SEQ + q0) * (N_HEADS * HEAD_DIM) + hq * HEAD_DIM;
    const float* kbase = kvg + ((size_t)b * SEQ) * KV_N + kvh * HEAD_DIM;
    const float* vbase = kbase + 256;

    // load Q tile (scale folded), packed split-bf16
    for (int idx = tid; idx < 64 * 32; idx += 256) {
        int r = idx >> 5, c4 = (idx & 31) << 2;
        float4 v = *(const float4*)(qbase + (size_t)r * (N_HEADS * HEAD_DIM) + c4);
        *(uint4*)(Qs + r * AT_QS + c4) =
            make_uint4(pk(v.x * scale), pk(v.y * scale), pk(v.z * scale), pk(v.w * scale));
    }

    float m_i[4], l_i[4], o[2][4][4];
#pragma unroll
    for (int ih = 0; ih < 4; ih++) { m_i[ih] = -1e30f; l_i[ih] = 0.f; }
#pragma unroll
    for (int i = 0; i < 2; i++)
#pragma unroll
        for (int n = 0; n < 4; n++)
#pragma unroll
            for (int r = 0; r < 4; r++) o[i][n][r] = 0.f;

    for (int kc = 0; kc <= qi; kc++) {
        __syncthreads();   // (a) prior-iter reads of Ks/Vs done; Q store visible (1st iter)
        for (int idx = tid; idx < 64 * 32; idx += 256) {
            int r = idx >> 5, c4 = (idx & 31) << 2;
            float4 kv4 = *(const float4*)(kbase + (size_t)(kc * 64 + r) * KV_N + c4);
            *(uint4*)(Ks + r * AT_QS + c4) = make_uint4(pk(kv4.x), pk(kv4.y), pk(kv4.z), pk(kv4.w));
            float4 vv4 = *(const float4*)(vbase + (size_t)(kc * 64 + r) * KV_N + c4);
            *(uint4*)(Vs + r * AT_VS + c4) = make_uint4(pk(vv4.x), pk(vv4.y), pk(vv4.z), pk(vv4.w));
        }
        __syncthreads();   // (b)

        // ---- S = Q @ K^T (warp: 32 rows x 16 cols) ----
        float s[2][2][4];
#pragma unroll
        for (int i = 0; i < 2; i++)
#pragma unroll
            for (int n = 0; n < 2; n++)
#pragma unroll
                for (int r = 0; r < 4; r++) s[i][n][r] = 0.f;

#pragma unroll
        for (int kt = 0; kt < 8; kt++) {
            const int k16 = kt << 4;
            uint32_t ahi[2][4], alo[2][4], bhi[2][2], blo[2][2];
#pragma unroll
            for (int i = 0; i < 2; i++) {
                int rb = wm * 32 + i * 16 + g;
                uint2 u0 = *(const uint2*)(Qs + rb * AT_QS + k16 + 2 * t);
                uint2 u1 = *(const uint2*)(Qs + (rb + 8) * AT_QS + k16 + 2 * t);
                uint2 u2 = *(const uint2*)(Qs + rb * AT_QS + k16 + 8 + 2 * t);
                uint2 u3 = *(const uint2*)(Qs + (rb + 8) * AT_QS + k16 + 8 + 2 * t);
                ahi[i][0] = HIP(u0.x, u0.y); alo[i][0] = LOP(u0.x, u0.y);
                ahi[i][1] = HIP(u1.x, u1.y); alo[i][1] = LOP(u1.x, u1.y);
                ahi[i][2] = HIP(u2.x, u2.y); alo[i][2] = LOP(u2.x, u2.y);
                ahi[i][3] = HIP(u3.x, u3.y); alo[i][3] = LOP(u3.x, u3.y);
            }
#pragma unroll
            for (int n = 0; n < 2; n++) {
                int cb = wn * 16 + n * 8 + g;
                uint2 v0 = *(const uint2*)(Ks + cb * AT_QS + k16 + 2 * t);
                uint2 v1 = *(const uint2*)(Ks + cb * AT_QS + k16 + 8 + 2 * t);
                bhi[n][0] = HIP(v0.x, v0.y); blo[n][0] = LOP(v0.x, v0.y);
                bhi[n][1] = HIP(v1.x, v1.y); blo[n][1] = LOP(v1.x, v1.y);
            }
#pragma unroll
            for (int i = 0; i < 2; i++)
#pragma unroll
                for (int n = 0; n < 2; n++) {
                    mma16(s[i][n], ahi[i][0], ahi[i][1], ahi[i][2], ahi[i][3], bhi[n][0], bhi[n][1]);
                    mma16(s[i][n], ahi[i][0], ahi[i][1], ahi[i][2], ahi[i][3], blo[n][0], blo[n][1]);
                    mma16(s[i][n], alo[i][0], alo[i][1], alo[i][2], alo[i][3], bhi[n][0], bhi[n][1]);
                }
        }

        // causal mask on diagonal tile
        if (kc == qi) {
#pragma unroll
            for (int i = 0; i < 2; i++)
#pragma unroll
                for (int h = 0; h < 2; h++) {
                    int r = q0 + wm * 32 + i * 16 + h * 8 + g;
#pragma unroll
                    for (int n = 0; n < 2; n++)
#pragma unroll
                        for (int z = 0; z < 2; z++) {
                            int cc = kc * 64 + wn * 16 + n * 8 + 2 * t + z;
                            if (cc > r) s[i][n][h * 2 + z] = -1e30f;
                        }
                }
        }

        // ---- warp-partial row max -> smem ----
#pragma unroll
        for (int i = 0; i < 2; i++)
#pragma unroll
            for (int h = 0; h < 2; h++) {
                float mx = fmaxf(fmaxf(s[i][0][h * 2], s[i][0][h * 2 + 1]),
                                 fmaxf(s[i][1][h * 2], s[i][1][h * 2 + 1]));
                mx = fmaxf(mx, __shfl_xor_sync(0xffffffffu, mx, 1));
                mx = fmaxf(mx, __shfl_xor_sync(0xffffffffu, mx, 2));
                if (t == 0) smax[wn * 64 + wm * 32 + i * 16 + h * 8 + g] = mx;
            }
        __syncthreads();   // (c)

        // ---- exp, P pack, partial sums ----
        float alpha[4];
#pragma unroll
        for (int i = 0; i < 2; i++)
#pragma unroll
            for (int h = 0; h < 2; h++) {
                int ih = i * 2 + h;
                int row = wm * 32 + i * 16 + h * 8 + g;
                float mt = fmaxf(fmaxf(smax[row], smax[64 + row]),
                                 fmaxf(smax[128 + row], smax[192 + row]));
                float mnew = fmaxf(m_i[ih], mt);
                alpha[ih] = __expf(m_i[ih] - mnew);
                m_i[ih] = mnew;
                float rs = 0.f;
#pragma unroll
                for (int n = 0; n < 2; n++) {
                    float e0 = __expf(s[i][n][h * 2] - mnew);
                    float e1 = __expf(s[i][n][h * 2 + 1] - mnew);
                    rs += e0 + e1;
                    *(uint2*)(Ps + row * AT_PS + wn * 16 + n * 8 + 2 * t) =
                        make_uint2(pk(e0), pk(e1));
                }
                rs += __shfl_xor_sync(0xffffffffu, rs, 1);
                rs += __shfl_xor_sync(0xffffffffu, rs, 2);
                if (t == 0) ssum[wn * 64 + row] = rs;
            }
        __syncthreads();   // (d)

        // ---- l update + O rescale ----
#pragma unroll
        for (int i = 0; i < 2; i++)
#pragma unroll
            for (int h = 0; h < 2; h++) {
                int ih = i * 2 + h;
                int row = wm * 32 + i * 16 + h * 8 + g;
                float ts = ssum[row] + ssum[64 + row] + ssum[128 + row] + ssum[192 + row];
                l_i[ih] = l_i[ih] * alpha[ih] + ts;
#pragma unroll
                for (int n = 0; n < 4; n++) {
                    o[i][n][h * 2] *= alpha[ih];
                    o[i][n][h * 2 + 1] *= alpha[ih];
                }
            }

        // ---- O += P @ V (warp: 32 rows x 32 cols) ----
#pragma unroll
        for (int kt = 0; kt < 4; kt++) {
            const int k16 = kt << 4;
            uint32_t ahi[2][4], alo[2][4];
#pragma unroll
            for (int i = 0; i < 2; i++) {
                int rb = wm * 32 + i * 16 + g;
                uint2 u0 = *(const uint2*)(Ps + rb * AT_PS + k16 + 2 * t);
                uint2 u1 = *(const uint2*)(Ps + (rb + 8) * AT_PS + k16 + 2 * t);
                uint2 u2 = *(const uint2*)(Ps + rb * AT_PS + k16 + 8 + 2 * t);
                uint2 u3 = *(const uint2*)(Ps + (rb + 8) * AT_PS + k16 + 8 + 2 * t);
                ahi[i][0] = HIP(u0.x, u0.y); alo[i][0] = LOP(u0.x, u0.y);
                ahi[i][1] = HIP(u1.x, u1.y); alo[i][1] = LOP(u1.x, u1.y);
                ahi[i][2] = HIP(u2.x, u2.y); alo[i][2] = LOP(u2.x, u2.y);
                ahi[i][3] = HIP(u3.x, u3.y); alo[i][3] = LOP(u3.x, u3.y);
            }
#pragma unroll
            for (int n = 0; n < 4; n++) {
                int nb = wn * 32 + n * 8 + g;
                uint32_t w0 = Vs[(k16 + 2 * t) * AT_VS + nb];
                uint32_t w1 = Vs[(k16 + 2 * t + 1) * AT_VS + nb];
                uint32_t w2 = Vs[(k16 + 2 * t + 8) * AT_VS + nb];
                uint32_t w3 = Vs[(k16 + 2 * t + 9) * AT_VS + nb];
                uint32_t bh0 = HIP(w0, w1), bl0 = LOP(w0, w1);
                uint32_t bh1 = HIP(w2, w3), bl1 = LOP(w2, w3);
#pragma unroll
                for (int i = 0; i < 2; i++) {
                    mma16(o[i][n], ahi[i][0], ahi[i][1], ahi[i][2], ahi[i][3], bh0, bh1);
                    mma16(o[i][n], ahi[i][0], ahi[i][1], ahi[i][2], ahi[i][3], bl0, bl1);
                    mma16(o[i][n], alo[i][0], alo[i][1], alo[i][2], alo[i][3], bh0, bh1);
                }
            }
        }
    }

    // epilogue
    float* ybase = yg + ((size_t)b * SEQ + q0) * (N_HEADS * HEAD_DIM) + hq * HEAD_DIM;
#pragma unroll
    for (int i = 0; i < 2; i++)
#pragma unroll
        for (int h = 0; h < 2; h++) {
            int ih = i * 2 + h;
            int row = wm * 32 + i * 16 + h * 8 + g;
            float inv = 1.f / l_i[ih];
#pragma unroll
            for (int n = 0; n < 4; n++) {
                int cc = wn * 32 + n * 8 + 2 * t;
                *(float2*)(ybase + (size_t)row * (N_HEADS * HEAD_DIM) + cc) =
                    make_float2(o[i][n][h * 2] * inv, o[i][n][h * 2 + 1] * inv);
            }
        }
}

// ---------------- launch ----------------
extern "C" void kernel_launch(void* const* d_in, const int* in_sizes, int n_in,
                              void* d_out, int out_size) {
    const float* x   = (const float*)d_in[0];
    const float* wq  = (const float*)d_in[1];
    const float* wkd = (const float*)d_in[2];
    const float* wvd = (const float*)d_in[3];
    const float* wku = (const float*)d_in[4];
    const float* wvu = (const float*)d_in[5];
    const float* wo  = (const float*)d_in[6];
    float* out = (float*)d_out;

    float* scratch = nullptr;
    cudaGetSymbolAddress((void**)&scratch, g_scratch);
    float* qb   = scratch + OFF_Q;
    float* kvb  = scratch + OFF_KV;
    float* yb   = scratch + OFF_Y;
    float* wkve = scratch + OFF_WKVE;

    eff_weights_kernel<<<2048, 256>>>(wkd, wvd, wku, wvu, wkve);

    cudaFuncSetAttribute(mm_bf16x2, cudaFuncAttributeMaxDynamicSharedMemorySize, MM_SMEM);
    mm_bf16x2<<<dim3(1024 / 128, M_TOK / 128), 256, MM_SMEM>>>(M_TOK, 1024, D_MODEL, x, wq, qb);
    mm_bf16x2<<<dim3(KV_N / 128, M_TOK / 128), 256, MM_SMEM>>>(M_TOK, KV_N, D_MODEL, x, wkve, kvb);

    cudaFuncSetAttribute(flash_mma_kernel, cudaFuncAttributeMaxDynamicSharedMemorySize, AT_SMEM);
    flash_mma_kernel<<<dim3(SEQ / 64, N_HEADS, BATCH), 256, AT_SMEM>>>(qb, kvb, yb);

    mm_bf16x2<<<dim3(1024 / 128, M_TOK / 128), 256, MM_SMEM>>>(M_TOK, 1024, 1024, yb, wo, out);
}

// round 5
// speedup vs baseline: 2.9224x; 1.1171x over previous
#include <cuda_runtime.h>
#include <cuda_bf16.h>
#include <cstdint>

// Problem constants
#define D_MODEL 1024
#define N_HEADS 8
#define N_KV 2
#define HEAD_DIM 128
#define D_LAT 32
#define BATCH 2
#define SEQ 2048
#define M_TOK (BATCH*SEQ)          // 4096
#define KV_N 512                   // fused K|V width

// ---------------- scratch ----------------
#define OFF_Q   0
#define OFF_KV  (4096*1024)
#define OFF_Y   (OFF_KV + 4096*512)
#define OFF_WKVE (OFF_Y + 4096*1024)
#define SCRATCH_FLOATS (OFF_WKVE + 1024*512)
__device__ float g_scratch[SCRATCH_FLOATS];

// ---------------- split-bf16 helpers ----------------
__device__ __forceinline__ uint32_t pk(float x) {
    __nv_bfloat16 h = __float2bfloat16(x);
    float hf = __bfloat162float(h);
    __nv_bfloat16 l = __float2bfloat16(x - hf);
    return ((uint32_t)__bfloat16_as_ushort(l) << 16) | (uint32_t)__bfloat16_as_ushort(h);
}
__device__ __forceinline__ void pksplit(float x, float y, uint32_t& hi, uint32_t& lo) {
    __nv_bfloat16 hx = __float2bfloat16(x), hy = __float2bfloat16(y);
    float rx = x - __bfloat162float(hx), ry = y - __bfloat162float(hy);
    hi = ((uint32_t)__bfloat16_as_ushort(hy) << 16) | (uint32_t)__bfloat16_as_ushort(hx);
    lo = ((uint32_t)__bfloat16_as_ushort(__float2bfloat16(ry)) << 16) |
         (uint32_t)__bfloat16_as_ushort(__float2bfloat16(rx));
}
#define HIP(u0,u1) __byte_perm((u0),(u1),0x5410)
#define LOP(u0,u1) __byte_perm((u0),(u1),0x7632)

__device__ __forceinline__ void mma16(float* c, uint32_t a0, uint32_t a1, uint32_t a2, uint32_t a3,
                                      uint32_t b0, uint32_t b1) {
    asm volatile(
        "mma.sync.aligned.m16n8k16.row.col.f32.bf16.bf16.f32 "
        "{%0,%1,%2,%3},{%4,%5,%6,%7},{%8,%9},{%0,%1,%2,%3};"
        : "+f"(c[0]), "+f"(c[1]), "+f"(c[2]), "+f"(c[3])
        : "r"(a0), "r"(a1), "r"(a2), "r"(a3), "r"(b0), "r"(b1));
}

// ---------------- effective fused up-projected weights ----------------
__global__ void eff_weights_kernel(const float* __restrict__ wkd,
                                   const float* __restrict__ wvd,
                                   const float* __restrict__ wku,
                                   const float* __restrict__ wvu,
                                   float* __restrict__ wkve) {
    int idx = blockIdx.x * blockDim.x + threadIdx.x;   // 1024*512
    int c = idx >> 9;
    int n = idx & 511;
    int which = n >> 8;
    int hd = n & 255;
    int h = hd >> 7;
    int d = hd & 127;
    const float* wd = which ? wvd : wkd;
    const float* wu = which ? wvu : wku;
    float s = 0.f;
#pragma unroll
    for (int l = 0; l < D_LAT; l++)
        s += wd[c * (N_KV * D_LAT) + h * D_LAT + l] * wu[l * HEAD_DIM + d];
    wkve[idx] = s;
}

// ---------------- split-bf16 GEMM: C[M,N] = A[M,K] @ B[K,N] ----------------
#define MM_AS 40
#define MM_BS 140
#define MM_AT (128*MM_AS)
#define MM_BT (32*MM_BS)
#define MM_SMEM ((2*MM_AT + 2*MM_BT)*4)

__global__ __launch_bounds__(256) void mm_bf16x2(int M, int N, int K,
                                                 const float* __restrict__ A,
                                                 const float* __restrict__ B,
                                                 float* __restrict__ C) {
    extern __shared__ uint32_t smu[];
    uint32_t* As = smu;
    uint32_t* Bs = smu + 2 * MM_AT;

    const int tid = threadIdx.x;
    const int w = tid >> 5;
    const int wm = w & 1;
    const int wn = w >> 1;
    const int lane = tid & 31;
    const int g = lane >> 2;
    const int t = lane & 3;
    const int row0 = blockIdx.y * 128;
    const int col0 = blockIdx.x * 128;

    const int ar = tid >> 3;
    const int ac = (tid & 7) << 2;
    const int br = tid >> 5;
    const int bc = (tid & 31) << 2;

    float4 la[4], lb[4];
    auto gload = [&](int kt) {
#pragma unroll
        for (int i = 0; i < 4; i++)
            la[i] = *(const float4*)(A + (size_t)(row0 + ar + 32 * i) * K + kt + ac);
#pragma unroll
        for (int i = 0; i < 4; i++)
            lb[i] = *(const float4*)(B + (size_t)(kt + br + 8 * i) * N + col0 + bc);
    };
    auto sstore = [&](int p) {
        uint32_t* Ap = As + p * MM_AT;
        uint32_t* Bp = Bs + p * MM_BT;
#pragma unroll
        for (int i = 0; i < 4; i++) {
            uint4 u = make_uint4(pk(la[i].x), pk(la[i].y), pk(la[i].z), pk(la[i].w));
            *(uint4*)(Ap + (ar + 32 * i) * MM_AS + ac) = u;
        }
#pragma unroll
        for (int i = 0; i < 4; i++) {
            uint4 u = make_uint4(pk(lb[i].x), pk(lb[i].y), pk(lb[i].z), pk(lb[i].w));
            *(uint4*)(Bp + (br + 8 * i) * MM_BS + bc) = u;
        }
    };

    float c[4][4][4];
#pragma unroll
    for (int i = 0; i < 4; i++)
#pragma unroll
        for (int j = 0; j < 4; j++)
#pragma unroll
            for (int r = 0; r < 4; r++) c[i][j][r] = 0.f;

    const int nt = K >> 5;
    gload(0);
    sstore(0);
    __syncthreads();

    for (int tt = 0; tt < nt; tt++) {
        if (tt + 1 < nt) gload((tt + 1) << 5);
        const uint32_t* Ap = As + (tt & 1) * MM_AT;
        const uint32_t* Bp = Bs + (tt & 1) * MM_BT;
#pragma unroll
        for (int kk = 0; kk < 2; kk++) {
            const int k16 = kk << 4;
            uint32_t ahi[4][4], alo[4][4], bhi[4][2], blo[4][2];
#pragma unroll
            for (int i = 0; i < 4; i++) {
                int rb = wm * 64 + i * 16 + g;
                uint2 u0 = *(const uint2*)(Ap + rb * MM_AS + k16 + 2 * t);
                uint2 u1 = *(const uint2*)(Ap + (rb + 8) * MM_AS + k16 + 2 * t);
                uint2 u2 = *(const uint2*)(Ap + rb * MM_AS + k16 + 8 + 2 * t);
                uint2 u3 = *(const uint2*)(Ap + (rb + 8) * MM_AS + k16 + 8 + 2 * t);
                ahi[i][0] = HIP(u0.x, u0.y); alo[i][0] = LOP(u0.x, u0.y);
                ahi[i][1] = HIP(u1.x, u1.y); alo[i][1] = LOP(u1.x, u1.y);
                ahi[i][2] = HIP(u2.x, u2.y); alo[i][2] = LOP(u2.x, u2.y);
                ahi[i][3] = HIP(u3.x, u3.y); alo[i][3] = LOP(u3.x, u3.y);
            }
#pragma unroll
            for (int j = 0; j < 4; j++) {
                int cb = wn * 32 + j * 8 + g;
                uint32_t u0 = Bp[(k16 + 2 * t) * MM_BS + cb];
                uint32_t u1 = Bp[(k16 + 2 * t + 1) * MM_BS + cb];
                uint32_t u2 = Bp[(k16 + 2 * t + 8) * MM_BS + cb];
                uint32_t u3 = Bp[(k16 + 2 * t + 9) * MM_BS + cb];
                bhi[j][0] = HIP(u0, u1); blo[j][0] = LOP(u0, u1);
                bhi[j][1] = HIP(u2, u3); blo[j][1] = LOP(u2, u3);
            }
#pragma unroll
            for (int i = 0; i < 4; i++)
#pragma unroll
                for (int j = 0; j < 4; j++) {
                    mma16(c[i][j], ahi[i][0], ahi[i][1], ahi[i][2], ahi[i][3], bhi[j][0], bhi[j][1]);
                    mma16(c[i][j], ahi[i][0], ahi[i][1], ahi[i][2], ahi[i][3], blo[j][0], blo[j][1]);
                    mma16(c[i][j], alo[i][0], alo[i][1], alo[i][2], alo[i][3], bhi[j][0], bhi[j][1]);
                }
        }
        if (tt + 1 < nt) sstore((tt + 1) & 1);
        __syncthreads();
    }

#pragma unroll
    for (int i = 0; i < 4; i++) {
        int r = row0 + wm * 64 + i * 16 + g;
#pragma unroll
        for (int j = 0; j < 4; j++) {
            int cc = col0 + wn * 32 + j * 8 + t * 2;
            *(float2*)(C + (size_t)r * N + cc) = make_float2(c[i][j][0], c[i][j][1]);
            *(float2*)(C + (size_t)(r + 8) * N + cc) = make_float2(c[i][j][2], c[i][j][3]);
        }
    }
}

// ---------------- flash attention v2: BR=128, BC=64, warp-per-16-rows ----------------
// 8 warps, each owns 16 rows x full 64 cols of S -> in-warp softmax, register P.
#define FA_QS 136
#define FA_KS 136
#define FA_VS 140
#define FA_NQ (128*FA_QS)
#define FA_NK (64*FA_KS)
#define FA_NV (64*FA_VS)
#define FA_SMEM ((FA_NQ + FA_NK + FA_NV)*4)

__global__ __launch_bounds__(256, 1) void flash_mma2_kernel(const float* __restrict__ qg,
                                                            const float* __restrict__ kvg,
                                                            float* __restrict__ yg) {
    extern __shared__ uint32_t smu[];
    uint32_t* Qs = smu;                // 128 x FA_QS
    uint32_t* Ks = Qs + FA_NQ;         // 64 x FA_KS
    uint32_t* Vs = Ks + FA_NK;         // 64 x FA_VS

    const int qb = (SEQ / 128 - 1) - blockIdx.x;   // heavy tiles first
    const int hq = blockIdx.y;
    const int b  = blockIdx.z;
    const int kvh = hq >> 2;
    const int tid = threadIdx.x;
    const int w = tid >> 5;
    const int lane = tid & 31;
    const int g = lane >> 2;
    const int t = lane & 3;
    const int q0 = qb * 128;
    const float scale = 0.08838834764831845f;

    const float* qbase = qg + ((size_t)b * SEQ + q0) * (N_HEADS * HEAD_DIM) + hq * HEAD_DIM;
    const float* kbase = kvg + ((size_t)b * SEQ) * KV_N + kvh * HEAD_DIM;
    const float* vbase = kbase + 256;

    const int lr = tid >> 5;           // kv-tile load row base (8 rows per pass)
    const int lc = (tid & 31) << 2;    // col (float4)

    // load Q tile (scale folded)
    for (int idx = tid; idx < 128 * 32; idx += 256) {
        int r = idx >> 5, c4 = (idx & 31) << 2;
        float4 v = *(const float4*)(qbase + (size_t)r * (N_HEADS * HEAD_DIM) + c4);
        *(uint4*)(Qs + r * FA_QS + c4) =
            make_uint4(pk(v.x * scale), pk(v.y * scale), pk(v.z * scale), pk(v.w * scale));
    }
    // load K/V tile 0 directly
    {
        const float* kp = kbase;
        const float* vp = vbase;
#pragma unroll
        for (int i = 0; i < 8; i++) {
            int r = lr + 8 * i;
            float4 kv4 = *(const float4*)(kp + (size_t)r * KV_N + lc);
            *(uint4*)(Ks + r * FA_KS + lc) = make_uint4(pk(kv4.x), pk(kv4.y), pk(kv4.z), pk(kv4.w));
            float4 vv4 = *(const float4*)(vp + (size_t)r * KV_N + lc);
            *(uint4*)(Vs + r * FA_VS + lc) = make_uint4(pk(vv4.x), pk(vv4.y), pk(vv4.z), pk(vv4.w));
        }
    }
    __syncthreads();

    float m0 = -1e30f, m1 = -1e30f, l0 = 0.f, l1 = 0.f;
    float o[16][4];
#pragma unroll
    for (int n = 0; n < 16; n++)
#pragma unroll
        for (int r = 0; r < 4; r++) o[n][r] = 0.f;

    const int kend = 2 * qb + 1;
    const int rowg = q0 + w * 16 + g;   // this thread's first global row

    for (int kc = 0; kc <= kend; kc++) {
        const bool pf = (kc < kend);
        float4 kreg[8], vreg[8];
        // prefetch next K tile into registers (latency overlapped with S MMAs)
        if (pf) {
            const float* kp = kbase + (size_t)(kc + 1) * 64 * KV_N;
#pragma unroll
            for (int i = 0; i < 8; i++)
                kreg[i] = *(const float4*)(kp + (size_t)(lr + 8 * i) * KV_N + lc);
        }

        // ---- S = Q @ K^T : warp tile 16 x 64 ----
        float s[8][4];
#pragma unroll
        for (int n = 0; n < 8; n++)
#pragma unroll
            for (int r = 0; r < 4; r++) s[n][r] = 0.f;

#pragma unroll
        for (int kt = 0; kt < 8; kt++) {
            const int k16 = kt << 4;
            const int rb = w * 16 + g;
            uint2 u0 = *(const uint2*)(Qs + rb * FA_QS + k16 + 2 * t);
            uint2 u1 = *(const uint2*)(Qs + (rb + 8) * FA_QS + k16 + 2 * t);
            uint2 u2 = *(const uint2*)(Qs + rb * FA_QS + k16 + 8 + 2 * t);
            uint2 u3 = *(const uint2*)(Qs + (rb + 8) * FA_QS + k16 + 8 + 2 * t);
            uint32_t ah0 = HIP(u0.x, u0.y), al0 = LOP(u0.x, u0.y);
            uint32_t ah1 = HIP(u1.x, u1.y), al1 = LOP(u1.x, u1.y);
            uint32_t ah2 = HIP(u2.x, u2.y), al2 = LOP(u2.x, u2.y);
            uint32_t ah3 = HIP(u3.x, u3.y), al3 = LOP(u3.x, u3.y);
#pragma unroll
            for (int n = 0; n < 8; n++) {
                int cb = n * 8 + g;
                uint2 v0 = *(const uint2*)(Ks + cb * FA_KS + k16 + 2 * t);
                uint2 v1 = *(const uint2*)(Ks + cb * FA_KS + k16 + 8 + 2 * t);
                uint32_t bh0 = HIP(v0.x, v0.y), bl0 = LOP(v0.x, v0.y);
                uint32_t bh1 = HIP(v1.x, v1.y), bl1 = LOP(v1.x, v1.y);
                mma16(s[n], ah0, ah1, ah2, ah3, bh0, bh1);
                mma16(s[n], ah0, ah1, ah2, ah3, bl0, bl1);
                mma16(s[n], al0, al1, al2, al3, bh0, bh1);
            }
        }

        // prefetch next V tile into registers (overlaps softmax + PV)
        if (pf) {
            const float* vp = vbase + (size_t)(kc + 1) * 64 * KV_N;
#pragma unroll
            for (int i = 0; i < 8; i++)
                vreg[i] = *(const float4*)(vp + (size_t)(lr + 8 * i) * KV_N + lc);
        }

        // causal mask on the two diagonal-band tiles
        if (kc >= 2 * qb) {
#pragma unroll
            for (int n = 0; n < 8; n++) {
                int c0 = kc * 64 + n * 8 + 2 * t;
                if (c0 > rowg)      s[n][0] = -1e30f;
                if (c0 + 1 > rowg)  s[n][1] = -1e30f;
                if (c0 > rowg + 8)  s[n][2] = -1e30f;
                if (c0 + 1 > rowg + 8) s[n][3] = -1e30f;
            }
        }

        // ---- in-warp online softmax (rows g and g+8) ----
        float mx0 = -1e30f, mx1 = -1e30f;
#pragma unroll
        for (int n = 0; n < 8; n++) {
            mx0 = fmaxf(mx0, fmaxf(s[n][0], s[n][1]));
            mx1 = fmaxf(mx1, fmaxf(s[n][2], s[n][3]));
        }
        mx0 = fmaxf(mx0, __shfl_xor_sync(0xffffffffu, mx0, 1));
        mx0 = fmaxf(mx0, __shfl_xor_sync(0xffffffffu, mx0, 2));
        mx1 = fmaxf(mx1, __shfl_xor_sync(0xffffffffu, mx1, 1));
        mx1 = fmaxf(mx1, __shfl_xor_sync(0xffffffffu, mx1, 2));
        float mn0 = fmaxf(m0, mx0), mn1 = fmaxf(m1, mx1);
        float a0 = __expf(m0 - mn0), a1 = __expf(m1 - mn1);
        m0 = mn0; m1 = mn1;
        float rs0 = 0.f, rs1 = 0.f;
#pragma unroll
        for (int n = 0; n < 8; n++) {
            s[n][0] = __expf(s[n][0] - mn0);
            s[n][1] = __expf(s[n][1] - mn0);
            s[n][2] = __expf(s[n][2] - mn1);
            s[n][3] = __expf(s[n][3] - mn1);
            rs0 += s[n][0] + s[n][1];
            rs1 += s[n][2] + s[n][3];
        }
        rs0 += __shfl_xor_sync(0xffffffffu, rs0, 1);
        rs0 += __shfl_xor_sync(0xffffffffu, rs0, 2);
        rs1 += __shfl_xor_sync(0xffffffffu, rs1, 1);
        rs1 += __shfl_xor_sync(0xffffffffu, rs1, 2);
        l0 = l0 * a0 + rs0;
        l1 = l1 * a1 + rs1;
#pragma unroll
        for (int n = 0; n < 16; n++) {
            o[n][0] *= a0; o[n][1] *= a0;
            o[n][2] *= a1; o[n][3] *= a1;
        }

        // pack P fragments in registers (S frag layout == PV A-frag layout)
        uint32_t phi[4][4], plo[4][4];
#pragma unroll
        for (int kt = 0; kt < 4; kt++) {
            pksplit(s[2 * kt][0], s[2 * kt][1], phi[kt][0], plo[kt][0]);
            pksplit(s[2 * kt][2], s[2 * kt][3], phi[kt][1], plo[kt][1]);
            pksplit(s[2 * kt + 1][0], s[2 * kt + 1][1], phi[kt][2], plo[kt][2]);
            pksplit(s[2 * kt + 1][2], s[2 * kt + 1][3], phi[kt][3], plo[kt][3]);
        }

        // ---- O += P @ V : warp tile 16 x 128 ----
#pragma unroll
        for (int kt = 0; kt < 4; kt++) {
            const int k16 = kt << 4;
#pragma unroll
            for (int n = 0; n < 16; n++) {
                int nb = n * 8 + g;
                uint32_t w0 = Vs[(k16 + 2 * t) * FA_VS + nb];
                uint32_t w1 = Vs[(k16 + 2 * t + 1) * FA_VS + nb];
                uint32_t w2 = Vs[(k16 + 2 * t + 8) * FA_VS + nb];
                uint32_t w3 = Vs[(k16 + 2 * t + 9) * FA_VS + nb];
                uint32_t bh0 = HIP(w0, w1), bl0 = LOP(w0, w1);
                uint32_t bh1 = HIP(w2, w3), bl1 = LOP(w2, w3);
                mma16(o[n], phi[kt][0], phi[kt][1], phi[kt][2], phi[kt][3], bh0, bh1);
                mma16(o[n], phi[kt][0], phi[kt][1], phi[kt][2], phi[kt][3], bl0, bl1);
                mma16(o[n], plo[kt][0], plo[kt][1], plo[kt][2], plo[kt][3], bh0, bh1);
            }
        }

        // commit prefetched tile
        if (pf) {
            __syncthreads();
#pragma unroll
            for (int i = 0; i < 8; i++) {
                int r = lr + 8 * i;
                *(uint4*)(Ks + r * FA_KS + lc) =
                    make_uint4(pk(kreg[i].x), pk(kreg[i].y), pk(kreg[i].z), pk(kreg[i].w));
                *(uint4*)(Vs + r * FA_VS + lc) =
                    make_uint4(pk(vreg[i].x), pk(vreg[i].y), pk(vreg[i].z), pk(vreg[i].w));
            }
            __syncthreads();
        }
    }

    // epilogue
    float* ybase = yg + ((size_t)b * SEQ + q0) * (N_HEADS * HEAD_DIM) + hq * HEAD_DIM;
    const int row = w * 16 + g;
    float inv0 = 1.f / l0, inv1 = 1.f / l1;
#pragma unroll
    for (int n = 0; n < 16; n++) {
        int cc = n * 8 + 2 * t;
        *(float2*)(ybase + (size_t)row * (N_HEADS * HEAD_DIM) + cc) =
            make_float2(o[n][0] * inv0, o[n][1] * inv0);
        *(float2*)(ybase + (size_t)(row + 8) * (N_HEADS * HEAD_DIM) + cc) =
            make_float2(o[n][2] * inv1, o[n][3] * inv1);
    }
}

// ---------------- launch ----------------
extern "C" void kernel_launch(void* const* d_in, const int* in_sizes, int n_in,
                              void* d_out, int out_size) {
    const float* x   = (const float*)d_in[0];
    const float* wq  = (const float*)d_in[1];
    const float* wkd = (const float*)d_in[2];
    const float* wvd = (const float*)d_in[3];
    const float* wku = (const float*)d_in[4];
    const float* wvu = (const float*)d_in[5];
    const float* wo  = (const float*)d_in[6];
    float* out = (float*)d_out;

    float* scratch = nullptr;
    cudaGetSymbolAddress((void**)&scratch, g_scratch);
    float* qb   = scratch + OFF_Q;
    float* kvb  = scratch + OFF_KV;
    float* yb   = scratch + OFF_Y;
    float* wkve = scratch + OFF_WKVE;

    eff_weights_kernel<<<2048, 256>>>(wkd, wvd, wku, wvu, wkve);

    cudaFuncSetAttribute(mm_bf16x2, cudaFuncAttributeMaxDynamicSharedMemorySize, MM_SMEM);
    mm_bf16x2<<<dim3(1024 / 128, M_TOK / 128), 256, MM_SMEM>>>(M_TOK, 1024, D_MODEL, x, wq, qb);
    mm_bf16x2<<<dim3(KV_N / 128, M_TOK / 128), 256, MM_SMEM>>>(M_TOK, KV_N, D_MODEL, x, wkve, kvb);

    cudaFuncSetAttribute(flash_mma2_kernel, cudaFuncAttributeMaxDynamicSharedMemorySize, FA_SMEM);
    flash_mma2_kernel<<<dim3(SEQ / 128, N_HEADS, BATCH), 256, FA_SMEM>>>(qb, kvb, yb);

    mm_bf16x2<<<dim3(1024 / 128, M_TOK / 128), 256, MM_SMEM>>>(M_TOK, 1024, 1024, yb, wo, out);
}

// round 6
// speedup vs baseline: 3.1922x; 1.0923x over previous
#include <cuda_runtime.h>
#include <cuda_bf16.h>
#include <cstdint>

// Problem constants
#define D_MODEL 1024
#define N_HEADS 8
#define N_KV 2
#define HEAD_DIM 128
#define D_LAT 32
#define BATCH 2
#define SEQ 2048
#define M_TOK (BATCH*SEQ)          // 4096
#define KV_N 512                   // fused K|V width

// ---------------- scratch (4B words) ----------------
#define OFF_QH   0
#define OFF_QL   (OFF_QH + 4096*512)
#define OFF_KVH  (OFF_QL + 4096*512)
#define OFF_KVL  (OFF_KVH + 4096*256)
#define OFF_VTH  (OFF_KVL + 4096*256)
#define OFF_VTL  (OFF_VTH + 2*2*128*1024)
#define OFF_Y    (OFF_VTL + 2*2*128*1024)
#define OFF_WKVE (OFF_Y + 4096*1024)
#define SCRATCH_WORDS (OFF_WKVE + 1024*512)
__device__ float g_scratch[SCRATCH_WORDS];

// ---------------- split-bf16 helpers ----------------
__device__ __forceinline__ uint32_t pk(float x) {
    __nv_bfloat16 h = __float2bfloat16(x);
    float hf = __bfloat162float(h);
    __nv_bfloat16 l = __float2bfloat16(x - hf);
    return ((uint32_t)__bfloat16_as_ushort(l) << 16) | (uint32_t)__bfloat16_as_ushort(h);
}
// pack pair (x,y): hi = bf16x2(hy,hx) with x in low half; lo = residuals
__device__ __forceinline__ void pksplit(float x, float y, uint32_t& hi, uint32_t& lo) {
    __nv_bfloat16 hx = __float2bfloat16(x), hy = __float2bfloat16(y);
    float rx = x - __bfloat162float(hx), ry = y - __bfloat162float(hy);
    hi = ((uint32_t)__bfloat16_as_ushort(hy) << 16) | (uint32_t)__bfloat16_as_ushort(hx);
    lo = ((uint32_t)__bfloat16_as_ushort(__float2bfloat16(ry)) << 16) |
         (uint32_t)__bfloat16_as_ushort(__float2bfloat16(rx));
}
#define HIP(u0,u1) __byte_perm((u0),(u1),0x5410)
#define LOP(u0,u1) __byte_perm((u0),(u1),0x7632)

__device__ __forceinline__ void mma16(float* c, uint32_t a0, uint32_t a1, uint32_t a2, uint32_t a3,
                                      uint32_t b0, uint32_t b1) {
    asm volatile(
        "mma.sync.aligned.m16n8k16.row.col.f32.bf16.bf16.f32 "
        "{%0,%1,%2,%3},{%4,%5,%6,%7},{%8,%9},{%0,%1,%2,%3};"
        : "+f"(c[0]), "+f"(c[1]), "+f"(c[2]), "+f"(c[3])
        : "r"(a0), "r"(a1), "r"(a2), "r"(a3), "r"(b0), "r"(b1));
}

__device__ __forceinline__ void cpa16(uint32_t dst_smem, const uint32_t* src) {
    asm volatile("{ .reg .u64 p; cvta.to.global.u64 p, %1; cp.async.ca.shared.global [%0], [p], 16; }"
                 :: "r"(dst_smem), "l"(src));
}

// ---------------- effective fused up-projected weights ----------------
__global__ void eff_weights_kernel(const float* __restrict__ wkd,
                                   const float* __restrict__ wvd,
                                   const float* __restrict__ wku,
                                   const float* __restrict__ wvu,
                                   float* __restrict__ wkve) {
    int idx = blockIdx.x * blockDim.x + threadIdx.x;   // 1024*512
    int c = idx >> 9;
    int n = idx & 511;
    int which = n >> 8;
    int hd = n & 255;
    int h = hd >> 7;
    int d = hd & 127;
    const float* wd = which ? wvd : wkd;
    const float* wu = which ? wvu : wku;
    float s = 0.f;
#pragma unroll
    for (int l = 0; l < D_LAT; l++)
        s += wd[c * (N_KV * D_LAT) + h * D_LAT + l] * wu[l * HEAD_DIM + d];
    wkve[idx] = s;
}

// ---------------- split-bf16 GEMM core (shared by both epilogues) ----------------
#define MM_AS 40
#define MM_BS 140
#define MM_AT (128*MM_AS)
#define MM_BT (32*MM_BS)
#define MM_SMEM ((2*MM_AT + 2*MM_BT)*4)

// mainloop as a macro-like inline: computes c[4][4][4] for this block
#define MM_MAINLOOP(A, B, M, N, K)                                                          \
    extern __shared__ uint32_t smu[];                                                        \
    uint32_t* As = smu;                                                                      \
    uint32_t* Bs = smu + 2 * MM_AT;                                                          \
    const int tid = threadIdx.x;                                                             \
    const int w = tid >> 5;                                                                  \
    const int wm = w & 1;                                                                    \
    const int wn = w >> 1;                                                                   \
    const int lane = tid & 31;                                                               \
    const int g = lane >> 2;                                                                 \
    const int t = lane & 3;                                                                  \
    const int row0 = blockIdx.y * 128;                                                       \
    const int col0 = blockIdx.x * 128;                                                       \
    const int ar = tid >> 3;                                                                 \
    const int ac = (tid & 7) << 2;                                                           \
    const int br = tid >> 5;                                                                 \
    const int bc = (tid & 31) << 2;                                                          \
    float4 la[4], lb[4];                                                                     \
    auto gload = [&](int kt) {                                                               \
        _Pragma("unroll")                                                                    \
        for (int i = 0; i < 4; i++)                                                          \
            la[i] = *(const float4*)(A + (size_t)(row0 + ar + 32 * i) * K + kt + ac);        \
        _Pragma("unroll")                                                                    \
        for (int i = 0; i < 4; i++)                                                          \
            lb[i] = *(const float4*)(B + (size_t)(kt + br + 8 * i) * N + col0 + bc);         \
    };                                                                                       \
    auto sstore = [&](int p) {                                                               \
        uint32_t* Ap = As + p * MM_AT;                                                       \
        uint32_t* Bp = Bs + p * MM_BT;                                                       \
        _Pragma("unroll")                                                                    \
        for (int i = 0; i < 4; i++) {                                                        \
            uint4 u = make_uint4(pk(la[i].x), pk(la[i].y), pk(la[i].z), pk(la[i].w));        \
            *(uint4*)(Ap + (ar + 32 * i) * MM_AS + ac) = u;                                  \
        }                                                                                    \
        _Pragma("unroll")                                                                    \
        for (int i = 0; i < 4; i++) {                                                        \
            uint4 u = make_uint4(pk(lb[i].x), pk(lb[i].y), pk(lb[i].z), pk(lb[i].w));        \
            *(uint4*)(Bp + (br + 8 * i) * MM_BS + bc) = u;                                   \
        }                                                                                    \
    };                                                                                       \
    float c[4][4][4];                                                                        \
    _Pragma("unroll")                                                                        \
    for (int i = 0; i < 4; i++)                                                              \
        _Pragma("unroll")                                                                    \
        for (int j = 0; j < 4; j++)                                                          \
            _Pragma("unroll")                                                                \
            for (int r = 0; r < 4; r++) c[i][j][r] = 0.f;                                    \
    const int nt = K >> 5;                                                                   \
    gload(0);                                                                                \
    sstore(0);                                                                               \
    __syncthreads();                                                                         \
    for (int tt = 0; tt < nt; tt++) {                                                        \
        if (tt + 1 < nt) gload((tt + 1) << 5);                                               \
        const uint32_t* Ap = As + (tt & 1) * MM_AT;                                          \
        const uint32_t* Bp = Bs + (tt & 1) * MM_BT;                                          \
        _Pragma("unroll")                                                                    \
        for (int kk = 0; kk < 2; kk++) {                                                     \
            const int k16 = kk << 4;                                                         \
            uint32_t ahi[4][4], alo[4][4], bhi[4][2], blo[4][2];                             \
            _Pragma("unroll")                                                                \
            for (int i = 0; i < 4; i++) {                                                    \
                int rb = wm * 64 + i * 16 + g;                                               \
                uint2 u0 = *(const uint2*)(Ap + rb * MM_AS + k16 + 2 * t);                   \
                uint2 u1 = *(const uint2*)(Ap + (rb + 8) * MM_AS + k16 + 2 * t);             \
                uint2 u2 = *(const uint2*)(Ap + rb * MM_AS + k16 + 8 + 2 * t);               \
                uint2 u3 = *(const uint2*)(Ap + (rb + 8) * MM_AS + k16 + 8 + 2 * t);         \
                ahi[i][0] = HIP(u0.x, u0.y); alo[i][0] = LOP(u0.x, u0.y);                    \
                ahi[i][1] = HIP(u1.x, u1.y); alo[i][1] = LOP(u1.x, u1.y);                    \
                ahi[i][2] = HIP(u2.x, u2.y); alo[i][2] = LOP(u2.x, u2.y);                    \
                ahi[i][3] = HIP(u3.x, u3.y); alo[i][3] = LOP(u3.x, u3.y);                    \
            }                                                                                \
            _Pragma("unroll")                                                                \
            for (int j = 0; j < 4; j++) {                                                    \
                int cb = wn * 32 + j * 8 + g;                                                \
                uint32_t u0 = Bp[(k16 + 2 * t) * MM_BS + cb];                                \
                uint32_t u1 = Bp[(k16 + 2 * t + 1) * MM_BS + cb];                            \
                uint32_t u2 = Bp[(k16 + 2 * t + 8) * MM_BS + cb];                            \
                uint32_t u3 = Bp[(k16 + 2 * t + 9) * MM_BS + cb];                            \
                bhi[j][0] = HIP(u0, u1); blo[j][0] = LOP(u0, u1);                            \
                bhi[j][1] = HIP(u2, u3); blo[j][1] = LOP(u2, u3);                            \
            }                                                                                \
            _Pragma("unroll")                                                                \
            for (int i = 0; i < 4; i++)                                                      \
                _Pragma("unroll")                                                            \
                for (int j = 0; j < 4; j++) {                                                \
                    mma16(c[i][j], ahi[i][0], ahi[i][1], ahi[i][2], ahi[i][3], bhi[j][0], bhi[j][1]); \
                    mma16(c[i][j], ahi[i][0], ahi[i][1], ahi[i][2], ahi[i][3], blo[j][0], blo[j][1]); \
                    mma16(c[i][j], alo[i][0], alo[i][1], alo[i][2], alo[i][3], bhi[j][0], bhi[j][1]); \
                }                                                                            \
        }                                                                                    \
        if (tt + 1 < nt) sstore((tt + 1) & 1);                                               \
        __syncthreads();                                                                     \
    }

// fp32-output GEMM (out projection)
__global__ __launch_bounds__(256) void mm_bf16x2(int M, int N, int K,
                                                 const float* __restrict__ A,
                                                 const float* __restrict__ B,
                                                 float* __restrict__ C) {
    MM_MAINLOOP(A, B, M, N, K)
#pragma unroll
    for (int i = 0; i < 4; i++) {
        int r = row0 + wm * 64 + i * 16 + g;
#pragma unroll
        for (int j = 0; j < 4; j++) {
            int cc = col0 + wn * 32 + j * 8 + t * 2;
            *(float2*)(C + (size_t)r * N + cc) = make_float2(c[i][j][0], c[i][j][1]);
            *(float2*)(C + (size_t)(r + 8) * N + cc) = make_float2(c[i][j][2], c[i][j][3]);
        }
    }
}

// plane-output GEMM (Q / KV projections): writes split-bf16 hi/lo planes, pair-packed along N
__global__ __launch_bounds__(256) void mm_planes(int M, int N, int K,
                                                 const float* __restrict__ A,
                                                 const float* __restrict__ B,
                                                 uint32_t* __restrict__ Ph,
                                                 uint32_t* __restrict__ Pl,
                                                 float scale) {
    MM_MAINLOOP(A, B, M, N, K)
    const int np = N >> 1;
#pragma unroll
    for (int i = 0; i < 4; i++) {
        int r = row0 + wm * 64 + i * 16 + g;
#pragma unroll
        for (int j = 0; j < 4; j++) {
            int cc = col0 + wn * 32 + j * 8 + t * 2;
            uint32_t h0, l0, h1, l1;
            pksplit(c[i][j][0] * scale, c[i][j][1] * scale, h0, l0);
            pksplit(c[i][j][2] * scale, c[i][j][3] * scale, h1, l1);
            Ph[(size_t)r * np + (cc >> 1)] = h0;
            Pl[(size_t)r * np + (cc >> 1)] = l0;
            Ph[(size_t)(r + 8) * np + (cc >> 1)] = h1;
            Pl[(size_t)(r + 8) * np + (cc >> 1)] = l1;
        }
    }
}

// ---------------- V transpose: KV planes [token][dpair] -> VT planes [d][tokenpair] ----------------
__global__ __launch_bounds__(256) void vtrans_kernel(const uint32_t* __restrict__ kvh,
                                                     const uint32_t* __restrict__ kvl,
                                                     uint32_t* __restrict__ vth,
                                                     uint32_t* __restrict__ vtl) {
    __shared__ uint32_t tile[64][65];
    const int t0 = blockIdx.x * 64;        // token base
    const int kvhd = blockIdx.y;
    const int b = blockIdx.z;
    const int tid = threadIdx.x;
#pragma unroll
    for (int p = 0; p < 2; p++) {
        const uint32_t* src = p ? kvl : kvh;
        uint32_t* dst = p ? vtl : vth;
#pragma unroll
        for (int i = 0; i < 16; i++) {
            int idx = i * 256 + tid;
            int r = idx >> 6, cx = idx & 63;
            tile[r][cx] = src[(size_t)(b * SEQ + t0 + r) * 256 + 128 + kvhd * 64 + cx];
        }
        __syncthreads();
#pragma unroll
        for (int i = 0; i < 16; i++) {
            int idx = i * 256 + tid;
            int d = idx >> 5, tpl = idx & 31;
            uint32_t u0 = tile[2 * tpl][d >> 1];
            uint32_t u1 = tile[2 * tpl + 1][d >> 1];
            uint32_t res = (d & 1) ? LOP(u0, u1) : HIP(u0, u1);
            dst[(size_t)((b * N_KV + kvhd) * 128 + d) * 1024 + (t0 >> 1) + tpl] = res;
        }
        __syncthreads();
    }
}

// ---------------- flash attention v3: pre-split planes, cp.async double buffer ----------------
#define FQ_ST 68
#define FK_ST 68
#define FV_ST 36
#define SM_QH 0
#define SM_QL (128*FQ_ST)
#define SM_K  (2*128*FQ_ST)
#define SM_KBUF (2*64*FK_ST)
#define SM_V  (SM_K + 2*SM_KBUF)
#define SM_VBUF (2*128*FV_ST)
#define FA3_SMEM ((SM_V + 2*SM_VBUF)*4)     // 212992 bytes

__global__ __launch_bounds__(256, 1) void flash3_kernel(const uint32_t* __restrict__ qh,
                                                        const uint32_t* __restrict__ ql,
                                                        const uint32_t* __restrict__ kvh,
                                                        const uint32_t* __restrict__ kvl,
                                                        const uint32_t* __restrict__ vth,
                                                        const uint32_t* __restrict__ vtl,
                                                        float* __restrict__ yg) {
    extern __shared__ uint32_t sm[];
    const uint32_t smb = (uint32_t)__cvta_generic_to_shared(sm);

    const int qb = (SEQ / 128 - 1) - blockIdx.x;   // heavy tiles first
    const int hq = blockIdx.y;
    const int b  = blockIdx.z;
    const int kvhd = hq >> 2;
    const int tid = threadIdx.x;
    const int w = tid >> 5;
    const int lane = tid & 31;
    const int g = lane >> 2;
    const int t = lane & 3;
    const int q0 = qb * 128;

    // ---- prologue: async-copy Q planes + K/V tile 0 ----
#pragma unroll
    for (int i = 0; i < 16; i++) {
        int idx = i * 256 + tid;
        int plane = idx >> 11;
        int r = (idx >> 4) & 127;
        int ch = (idx & 15) << 2;
        const uint32_t* src = (plane ? ql : qh) + (size_t)(b * SEQ + q0 + r) * 512 + hq * 64 + ch;
        cpa16(smb + (SM_QH + plane * (128 * FQ_ST) + r * FQ_ST + ch) * 4, src);
    }
    auto fill_kv = [&](int kt, int buf) {
#pragma unroll
        for (int i = 0; i < 8; i++) {
            int idx = i * 256 + tid;
            int plane = idx >> 10;
            int r = (idx >> 4) & 63;
            int ch = (idx & 15) << 2;
            const uint32_t* src = (plane ? kvl : kvh) +
                                  (size_t)(b * SEQ + kt * 64 + r) * 256 + kvhd * 64 + ch;
            cpa16(smb + (SM_K + buf * SM_KBUF + plane * (64 * FK_ST) + r * FK_ST + ch) * 4, src);
        }
#pragma unroll
        for (int i = 0; i < 8; i++) {
            int idx = i * 256 + tid;
            int plane = idx >> 10;
            int d = (idx >> 3) & 127;
            int ch = (idx & 7) << 2;
            const uint32_t* src = (plane ? vtl : vth) +
                                  (size_t)((b * N_KV + kvhd) * 128 + d) * 1024 + kt * 32 + ch;
            cpa16(smb + (SM_V + buf * SM_VBUF + plane * (128 * FV_ST) + d * FV_ST + ch) * 4, src);
        }
    };
    fill_kv(0, 0);
    asm volatile("cp.async.commit_group;");
    asm volatile("cp.async.wait_group 0;");
    __syncthreads();

    const uint32_t* QH = sm;
    const uint32_t* QL = sm + SM_QL;

    float m0 = -1e30f, m1 = -1e30f, l0 = 0.f, l1 = 0.f;
    float o[16][4];
#pragma unroll
    for (int n = 0; n < 16; n++)
#pragma unroll
        for (int r = 0; r < 4; r++) o[n][r] = 0.f;

    const int kend = 2 * qb + 1;
    const int rowg = q0 + w * 16 + g;

    for (int kc = 0; kc <= kend; kc++) {
        if (kc < kend) {
            fill_kv(kc + 1, (kc + 1) & 1);
            asm volatile("cp.async.commit_group;");
        }
        const uint32_t* KH = sm + SM_K + (kc & 1) * SM_KBUF;
        const uint32_t* KL = KH + 64 * FK_ST;
        const uint32_t* VH = sm + SM_V + (kc & 1) * SM_VBUF;
        const uint32_t* VL = VH + 128 * FV_ST;

        // ---- S = Q @ K^T : warp tile 16 x 64, zero perms ----
        float s[8][4];
#pragma unroll
        for (int n = 0; n < 8; n++)
#pragma unroll
            for (int r = 0; r < 4; r++) s[n][r] = 0.f;

        const int rb = w * 16 + g;
#pragma unroll
        for (int kt = 0; kt < 8; kt++) {
            const int kbase = kt * 8 + t;
            uint32_t ah0 = QH[rb * FQ_ST + kbase];
            uint32_t ah1 = QH[(rb + 8) * FQ_ST + kbase];
            uint32_t ah2 = QH[rb * FQ_ST + kbase + 4];
            uint32_t ah3 = QH[(rb + 8) * FQ_ST + kbase + 4];
            uint32_t al0 = QL[rb * FQ_ST + kbase];
            uint32_t al1 = QL[(rb + 8) * FQ_ST + kbase];
            uint32_t al2 = QL[rb * FQ_ST + kbase + 4];
            uint32_t al3 = QL[(rb + 8) * FQ_ST + kbase + 4];
#pragma unroll
            for (int n = 0; n < 8; n++) {
                const int cb = n * 8 + g;
                uint32_t bh0 = KH[cb * FK_ST + kbase];
                uint32_t bh1 = KH[cb * FK_ST + kbase + 4];
                uint32_t bl0 = KL[cb * FK_ST + kbase];
                uint32_t bl1 = KL[cb * FK_ST + kbase + 4];
                mma16(s[n], ah0, ah1, ah2, ah3, bh0, bh1);
                mma16(s[n], ah0, ah1, ah2, ah3, bl0, bl1);
                mma16(s[n], al0, al1, al2, al3, bh0, bh1);
            }
        }

        // causal mask on diagonal-band tiles
        if (kc >= 2 * qb) {
#pragma unroll
            for (int n = 0; n < 8; n++) {
                int c0 = kc * 64 + n * 8 + 2 * t;
                if (c0 > rowg)          s[n][0] = -1e30f;
                if (c0 + 1 > rowg)      s[n][1] = -1e30f;
                if (c0 > rowg + 8)      s[n][2] = -1e30f;
                if (c0 + 1 > rowg + 8)  s[n][3] = -1e30f;
            }
        }

        // ---- in-warp online softmax ----
        float mx0 = -1e30f, mx1 = -1e30f;
#pragma unroll
        for (int n = 0; n < 8; n++) {
            mx0 = fmaxf(mx0, fmaxf(s[n][0], s[n][1]));
            mx1 = fmaxf(mx1, fmaxf(s[n][2], s[n][3]));
        }
        mx0 = fmaxf(mx0, __shfl_xor_sync(0xffffffffu, mx0, 1));
        mx0 = fmaxf(mx0, __shfl_xor_sync(0xffffffffu, mx0, 2));
        mx1 = fmaxf(mx1, __shfl_xor_sync(0xffffffffu, mx1, 1));
        mx1 = fmaxf(mx1, __shfl_xor_sync(0xffffffffu, mx1, 2));
        float mn0 = fmaxf(m0, mx0), mn1 = fmaxf(m1, mx1);
        float a0 = __expf(m0 - mn0), a1 = __expf(m1 - mn1);
        m0 = mn0; m1 = mn1;
        float rs0 = 0.f, rs1 = 0.f;
#pragma unroll
        for (int n = 0; n < 8; n++) {
            s[n][0] = __expf(s[n][0] - mn0);
            s[n][1] = __expf(s[n][1] - mn0);
            s[n][2] = __expf(s[n][2] - mn1);
            s[n][3] = __expf(s[n][3] - mn1);
            rs0 += s[n][0] + s[n][1];
            rs1 += s[n][2] + s[n][3];
        }
        rs0 += __shfl_xor_sync(0xffffffffu, rs0, 1);
        rs0 += __shfl_xor_sync(0xffffffffu, rs0, 2);
        rs1 += __shfl_xor_sync(0xffffffffu, rs1, 1);
        rs1 += __shfl_xor_sync(0xffffffffu, rs1, 2);
        l0 = l0 * a0 + rs0;
        l1 = l1 * a1 + rs1;
#pragma unroll
        for (int n = 0; n < 16; n++) {
            o[n][0] *= a0; o[n][1] *= a0;
            o[n][2] *= a1; o[n][3] *= a1;
        }

        // pack P fragments in registers (S frag layout == PV A-frag layout)
        uint32_t phi[4][4], plo[4][4];
#pragma unroll
        for (int kt = 0; kt < 4; kt++) {
            pksplit(s[2 * kt][0], s[2 * kt][1], phi[kt][0], plo[kt][0]);
            pksplit(s[2 * kt][2], s[2 * kt][3], phi[kt][1], plo[kt][1]);
            pksplit(s[2 * kt + 1][0], s[2 * kt + 1][1], phi[kt][2], plo[kt][2]);
            pksplit(s[2 * kt + 1][2], s[2 * kt + 1][3], phi[kt][3], plo[kt][3]);
        }

        // ---- O += P @ V : warp tile 16 x 128, zero perms ----
#pragma unroll
        for (int kt = 0; kt < 4; kt++) {
            const int kb = kt * 8 + t;
#pragma unroll
            for (int n = 0; n < 16; n++) {
                const int nb = n * 8 + g;
                uint32_t bh0 = VH[nb * FV_ST + kb];
                uint32_t bh1 = VH[nb * FV_ST + kb + 4];
                uint32_t bl0 = VL[nb * FV_ST + kb];
                uint32_t bl1 = VL[nb * FV_ST + kb + 4];
                mma16(o[n], phi[kt][0], phi[kt][1], phi[kt][2], phi[kt][3], bh0, bh1);
                mma16(o[n], phi[kt][0], phi[kt][1], phi[kt][2], phi[kt][3], bl0, bl1);
                mma16(o[n], plo[kt][0], plo[kt][1], plo[kt][2], plo[kt][3], bh0, bh1);
            }
        }

        if (kc < kend) {
            asm volatile("cp.async.wait_group 0;");
            __syncthreads();
        }
    }

    // epilogue
    float* ybase = yg + ((size_t)b * SEQ + q0) * (N_HEADS * HEAD_DIM) + hq * HEAD_DIM;
    const int row = w * 16 + g;
    float inv0 = 1.f / l0, inv1 = 1.f / l1;
#pragma unroll
    for (int n = 0; n < 16; n++) {
        int cc = n * 8 + 2 * t;
        *(float2*)(ybase + (size_t)row * (N_HEADS * HEAD_DIM) + cc) =
            make_float2(o[n][0] * inv0, o[n][1] * inv0);
        *(float2*)(ybase + (size_t)(row + 8) * (N_HEADS * HEAD_DIM) + cc) =
            make_float2(o[n][2] * inv1, o[n][3] * inv1);
    }
}

// ---------------- launch ----------------
extern "C" void kernel_launch(void* const* d_in, const int* in_sizes, int n_in,
                              void* d_out, int out_size) {
    const float* x   = (const float*)d_in[0];
    const float* wq  = (const float*)d_in[1];
    const float* wkd = (const float*)d_in[2];
    const float* wvd = (const float*)d_in[3];
    const float* wku = (const float*)d_in[4];
    const float* wvu = (const float*)d_in[5];
    const float* wo  = (const float*)d_in[6];
    float* out = (float*)d_out;

    float* scratch = nullptr;
    cudaGetSymbolAddress((void**)&scratch, g_scratch);
    uint32_t* qhg  = (uint32_t*)(scratch + OFF_QH);
    uint32_t* qlg  = (uint32_t*)(scratch + OFF_QL);
    uint32_t* kvhg = (uint32_t*)(scratch + OFF_KVH);
    uint32_t* kvlg = (uint32_t*)(scratch + OFF_KVL);
    uint32_t* vthg = (uint32_t*)(scratch + OFF_VTH);
    uint32_t* vtlg = (uint32_t*)(scratch + OFF_VTL);
    float* yb      = scratch + OFF_Y;
    float* wkve    = scratch + OFF_WKVE;

    const float scale = 0.08838834764831845f;   // 1/sqrt(128)

    eff_weights_kernel<<<2048, 256>>>(wkd, wvd, wku, wvu, wkve);

    cudaFuncSetAttribute(mm_planes, cudaFuncAttributeMaxDynamicSharedMemorySize, MM_SMEM);
    cudaFuncSetAttribute(mm_bf16x2, cudaFuncAttributeMaxDynamicSharedMemorySize, MM_SMEM);
    mm_planes<<<dim3(8, 32), 256, MM_SMEM>>>(M_TOK, 1024, D_MODEL, x, wq, qhg, qlg, scale);
    mm_planes<<<dim3(4, 32), 256, MM_SMEM>>>(M_TOK, KV_N, D_MODEL, x, wkve, kvhg, kvlg, 1.0f);

    vtrans_kernel<<<dim3(SEQ / 64, N_KV, BATCH), 256>>>(kvhg, kvlg, vthg, vtlg);

    cudaFuncSetAttribute(flash3_kernel, cudaFuncAttributeMaxDynamicSharedMemorySize, FA3_SMEM);
    flash3_kernel<<<dim3(SEQ / 128, N_HEADS, BATCH), 256, FA3_SMEM>>>(qhg, qlg, kvhg, kvlg,
                                                                      vthg, vtlg, yb);

    mm_bf16x2<<<dim3(8, 32), 256, MM_SMEM>>>(M_TOK, 1024, 1024, yb, wo, out);
}